// round 6
// baseline (speedup 1.0000x reference)
#include <cuda_runtime.h>

// TabNet encoder, fully fused, packed f32x2 math.
// One CTA = 48 rows, 384 threads (12 warps, 3/SMSP), 1 CTA/SM.
// prior lives in GMEM scratch (__device__ array); rest of state in SMEM (192KB).
// B=131072, D=256, UN=128 (2UN=256), ND=NA=64, NSTEPS=3.

#define TB 48            // rows per CTA
#define NTH 384          // threads per CTA
#define BMAX 131072

__device__ float g_prior[(size_t)BMAX * 256];

typedef unsigned long long u64;

__device__ __forceinline__ u64 dup2(float v) {
    u64 r; asm("mov.b64 %0,{%1,%1};" : "=l"(r) : "f"(v)); return r;
}
__device__ __forceinline__ void fma2_(u64& d, u64 a, u64 b) {
    asm("fma.rn.f32x2 %0,%1,%2,%3;" : "=l"(d) : "l"(a), "l"(b), "l"(d));
}
__device__ __forceinline__ float2 up2(u64 v) {
    float lo, hi; asm("mov.b64 {%0,%1},%2;" : "=f"(lo), "=f"(hi) : "l"(v));
    return make_float2(lo, hi);
}

__device__ __forceinline__ float sig_(float x) {
    return __fdividef(1.0f, 1.0f + __expf(-x));
}

// H[TB][256] = BN(act[TB][AS..K] @ W[K][256]); thread tile 8 rows x 4 cols.
// cg = t&63 -> cols 4cg.., rg = t>>6 (0..5) -> rows 8rg..
template<int K, int AS>
__device__ __forceinline__ void gemm_bn256(
    const float* __restrict__ W,
    const float* __restrict__ gg, const float* __restrict__ bb,
    const float* __restrict__ mm, const float* __restrict__ vv,
    const float* act, float* H)
{
    const int t  = threadIdx.x;
    const int cg = t & 63;
    const int c0 = cg << 2;
    const int r0 = (t >> 6) << 3;
    const float* actb = act + r0 * AS;
    // W row = 256 floats = 64 ulonglong2; this thread reads element cg of each row.
    const ulonglong2* W2 = reinterpret_cast<const ulonglong2*>(W) + cg;

    u64 acc[8][2];
#pragma unroll
    for (int r = 0; r < 8; r++) { acc[r][0] = 0ull; acc[r][1] = 0ull; }

    ulonglong2 w[4];
#pragma unroll
    for (int i = 0; i < 4; i++) w[i] = W2[i * 64];

#pragma unroll 1
    for (int k = 0; k < K; k += 4) {
        const int kn = (k + 4 < K) ? (k + 4) : k;
        ulonglong2 wn[4];
#pragma unroll
        for (int i = 0; i < 4; i++) wn[i] = W2[(kn + i) * 64];

#pragma unroll
        for (int rr = 0; rr < 8; rr++) {
            float4 a4 = *reinterpret_cast<const float4*>(actb + rr * AS + k);
            u64 ax = dup2(a4.x), ay = dup2(a4.y);
            u64 az = dup2(a4.z), aw = dup2(a4.w);
            fma2_(acc[rr][0], ax, w[0].x); fma2_(acc[rr][1], ax, w[0].y);
            fma2_(acc[rr][0], ay, w[1].x); fma2_(acc[rr][1], ay, w[1].y);
            fma2_(acc[rr][0], az, w[2].x); fma2_(acc[rr][1], az, w[2].y);
            fma2_(acc[rr][0], aw, w[3].x); fma2_(acc[rr][1], aw, w[3].y);
        }
#pragma unroll
        for (int i = 0; i < 4; i++) w[i] = wn[i];
    }

    // folded-BN epilogue
    float sc[4], bs[4];
#pragma unroll
    for (int cc = 0; cc < 4; cc++) {
        int c = c0 + cc;
        sc[cc] = gg[c] * rsqrtf(vv[c] + 1e-3f);
        bs[cc] = bb[c] - mm[c] * sc[cc];
    }
#pragma unroll
    for (int rr = 0; rr < 8; rr++) {
        float2 lo = up2(acc[rr][0]), hi = up2(acc[rr][1]);
        float4 o;
        o.x = fmaf(lo.x, sc[0], bs[0]);
        o.y = fmaf(lo.y, sc[1], bs[1]);
        o.z = fmaf(hi.x, sc[2], bs[2]);
        o.w = fmaf(hi.y, sc[3], bs[3]);
        *reinterpret_cast<float4*>(H + (r0 + rr) * 256 + c0) = o;
    }
}

// GLU over H[TB][256]: out = H[:, :128] * sigmoid(H[:, 128:]).
__device__ __forceinline__ void glu_step(const float* H, float* outp, int os,
                                         const float* addp, int as_, bool combine)
{
    const int t = threadIdx.x;
    const int u = t & 127;
    const int q = t >> 7;                 // 0..2
#pragma unroll
    for (int r8 = 0; r8 < TB / 3; r8++) {
        int r = q * (TB / 3) + r8;
        float a = H[r * 256 + u];
        float b = H[r * 256 + 128 + u];
        float gl = a * sig_(b);
        if (combine) gl = 0.70710678118654752f * (addp[r * as_ + u] + gl);
        outp[r * os + u] = gl;
    }
}

template<int AS>
__device__ __forceinline__ void shared_block_(const float* act,
    const float* W0, const float* W1,
    const float* g, const float* b, const float* m, const float* v,
    float* X, float* H, float* G)
{
    __syncthreads();
    gemm_bn256<256, AS>(W0, g, b, m, v, act, H);
    __syncthreads();
    glu_step(H, G, 128, (const float*)0, 0, false);      // G = glu1
    __syncthreads();
    gemm_bn256<128, 128>(W1, g + 256, b + 256, m + 256, v + 256, G, H);
    __syncthreads();
    glu_step(H, X, 256, G, 128, true);                   // X[:, :128] = s*(glu1+glu2)
    __syncthreads();
}

__device__ __forceinline__ void dep_block_(const float* Wd, const float* g, const float* b,
    const float* m, const float* v, float* X, float* H)
{
#pragma unroll
    for (int i = 0; i < 2; i++) {
        __syncthreads();
        gemm_bn256<128, 256>(Wd + i * 128 * 256, g + i * 256, b + i * 256,
                             m + i * 256, v + i * 256, X, H);
        __syncthreads();
        glu_step(H, X, 256, X, 256, true);               // X = s*(X + glu)
    }
    __syncthreads();
}

__device__ __forceinline__ void post_dep_(const float* X, float* aB, float* agg, bool addagg)
{
#pragma unroll
    for (int i = 0; i < TB * 64 / NTH; i++) {
        int lin = threadIdx.x + NTH * i;
        int r = lin >> 6, c = lin & 63;
        aB[r * 64 + c] = X[r * 256 + 64 + c];
        if (addagg) agg[r * 64 + c] += fmaxf(X[r * 256 + c], 0.0f);
    }
    __syncthreads();
}

// z = prior * bn_logits (in H); sparsemax via Michelot projection; one warp = 4 rows.
// prior read from / written to GMEM scratch; step 0 uses implicit prior=1.
__device__ __forceinline__ void attn_sparsemax_(const float* H, const float* feat,
                                                float* X, long long rowbase, int B,
                                                int step)
{
    const int warp = threadIdx.x >> 5;     // 0..11
    const int lane = threadIdx.x & 31;
#pragma unroll
    for (int rr = 0; rr < TB / 12; rr++) {
        const int r = warp * (TB / 12) + rr;
        long long gr = rowbase + r; if (gr >= B) gr = B - 1;
        float* pp = g_prior + gr * 256;

        float pv[8], z[8];
#pragma unroll
        for (int i = 0; i < 8; i++) {
            int e = lane + 32 * i;
            pv[i] = (step == 0) ? 1.0f : pp[e];
            z[i] = pv[i] * H[r * 256 + e];
        }
        unsigned am = 0xFFu;
        float tau = 0.0f;
        for (int it = 0; it < 64; it++) {
            float s = 0.0f, cnt = 0.0f;
#pragma unroll
            for (int i = 0; i < 8; i++)
                if (am & (1u << i)) { s += z[i]; cnt += 1.0f; }
#pragma unroll
            for (int o = 16; o >= 1; o >>= 1) {
                s   += __shfl_xor_sync(0xffffffffu, s, o);
                cnt += __shfl_xor_sync(0xffffffffu, cnt, o);
            }
            tau = __fdividef(s - 1.0f, cnt);
            unsigned na = 0u;
#pragma unroll
            for (int i = 0; i < 8; i++)
                if (z[i] > tau) na |= (1u << i);
            int changed = (na != am);
            am = na;
            if (!__any_sync(0xffffffffu, changed)) break;
        }
#pragma unroll
        for (int i = 0; i < 8; i++) {
            int e = lane + 32 * i;
            float mv = fmaxf(z[i] - tau, 0.0f);
            X[r * 256 + e] = mv * feat[r * 256 + e];
            if (step < 2) pp[e] = pv[i] * (1.3f - mv);   // last step's prior unused
        }
    }
    __syncthreads();
}

__global__ void __launch_bounds__(NTH, 1)
tabnet_fused(const float* __restrict__ inputs,
             const float* __restrict__ in_g, const float* __restrict__ in_b,
             const float* __restrict__ in_m, const float* __restrict__ in_v,
             const float* __restrict__ sh_W0, const float* __restrict__ sh_W1,
             const float* __restrict__ sh_g, const float* __restrict__ sh_b,
             const float* __restrict__ sh_m, const float* __restrict__ sh_v,
             const float* __restrict__ dep_W, const float* __restrict__ dep_g,
             const float* __restrict__ dep_b, const float* __restrict__ dep_m,
             const float* __restrict__ dep_v,
             const float* __restrict__ at_W, const float* __restrict__ at_g,
             const float* __restrict__ at_b, const float* __restrict__ at_m,
             const float* __restrict__ at_v,
             const float* __restrict__ Wout,
             float* __restrict__ out, int B)
{
    extern __shared__ float sm_[];
    float* feat  = sm_;                 // [TB][256]
    float* X     = feat  + TB * 256;    // [TB][256]
    float* H     = X     + TB * 256;    // [TB][256]
    float* G     = H     + TB * 256;    // [TB][128]
    float* aB    = G     + TB * 128;    // [TB][64]
    float* agg   = aB    + TB * 64;     // [TB][64]

    const int t = threadIdx.x;
    const long long rowbase = (long long)blockIdx.x * TB;

    // input BN -> feat; agg = 0
    {
        const float4* in4 = reinterpret_cast<const float4*>(inputs);
        const float4* g4  = reinterpret_cast<const float4*>(in_g);
        const float4* b4  = reinterpret_cast<const float4*>(in_b);
        const float4* m4  = reinterpret_cast<const float4*>(in_m);
        const float4* v4  = reinterpret_cast<const float4*>(in_v);
#pragma unroll
        for (int i = 0; i < TB * 64 / NTH; i++) {
            int lin = t + NTH * i;           // float4 index
            int r = lin >> 6, d4 = lin & 63;
            long long gr = rowbase + r; if (gr >= B) gr = B - 1;
            float4 xv = in4[gr * 64 + d4];
            float4 gv = g4[d4], bv = b4[d4], mv = m4[d4], vv = v4[d4];
            float4 o; float s;
            s = gv.x * rsqrtf(vv.x + 1e-3f); o.x = fmaf(xv.x - mv.x, s, bv.x);
            s = gv.y * rsqrtf(vv.y + 1e-3f); o.y = fmaf(xv.y - mv.y, s, bv.y);
            s = gv.z * rsqrtf(vv.z + 1e-3f); o.z = fmaf(xv.z - mv.z, s, bv.z);
            s = gv.w * rsqrtf(vv.w + 1e-3f); o.w = fmaf(xv.w - mv.w, s, bv.w);
            reinterpret_cast<float4*>(feat)[lin] = o;
        }
#pragma unroll
        for (int i = 0; i < (TB * 16 + NTH - 1) / NTH; i++) {
            int lin = t + NTH * i;
            if (lin < TB * 16)
                reinterpret_cast<float4*>(agg)[lin] = make_float4(0.f, 0.f, 0.f, 0.f);
        }
    }
    __syncthreads();

    // initial shared + dep block (no agg accumulation)
    shared_block_<256>(feat, sh_W0, sh_W1, sh_g, sh_b, sh_m, sh_v, X, H, G);
    dep_block_(dep_W, dep_g, dep_b, dep_m, dep_v, X, H);
    post_dep_(X, aB, agg, false);

    // 3 decision steps
    for (int s = 0; s < 3; s++) {
        __syncthreads();
        gemm_bn256<64, 64>(at_W + s * 64 * 256, at_g + s * 256, at_b + s * 256,
                           at_m + s * 256, at_v + s * 256, aB, H);
        __syncthreads();
        attn_sparsemax_(H, feat, X, rowbase, B, s);   // X = mask * feat
        shared_block_<256>(X, sh_W0, sh_W1, sh_g, sh_b, sh_m, sh_v, X, H, G);
        dep_block_(dep_W + (s + 1) * 2 * 128 * 256,
                   dep_g + (s + 1) * 512, dep_b + (s + 1) * 512,
                   dep_m + (s + 1) * 512, dep_v + (s + 1) * 512, X, H);
        post_dep_(X, aB, agg, true);
    }

    // out = agg @ Wout  (64x64); rgx = t>>6 (0..5) -> 8 rows each
    {
        const int c   = t & 63;
        const int rgx = t >> 6;
        float acc[8];
#pragma unroll
        for (int rr = 0; rr < 8; rr++) acc[rr] = 0.0f;
        for (int k = 0; k < 64; k += 4) {
#pragma unroll
            for (int kk = 0; kk < 4; kk++) {
                float wv_ = Wout[(k + kk) * 64 + c];
#pragma unroll
                for (int rr = 0; rr < 8; rr++)
                    acc[rr] = fmaf(agg[(rgx * 8 + rr) * 64 + (k + kk)], wv_, acc[rr]);
            }
        }
#pragma unroll
        for (int rr = 0; rr < 8; rr++) {
            long long gr = rowbase + rgx * 8 + rr;
            if (gr < B) out[gr * 64 + c] = acc[rr];
        }
    }
}

extern "C" void kernel_launch(void* const* d_in, const int* in_sizes, int n_in,
                              void* d_out, int out_size)
{
    const float* inputs = (const float*)d_in[0];
    const float* in_g   = (const float*)d_in[1];
    const float* in_b   = (const float*)d_in[2];
    const float* in_m   = (const float*)d_in[3];
    const float* in_v   = (const float*)d_in[4];
    const float* sh_W0  = (const float*)d_in[5];
    const float* sh_W1  = (const float*)d_in[6];
    const float* sh_g   = (const float*)d_in[7];
    const float* sh_b   = (const float*)d_in[8];
    const float* sh_m   = (const float*)d_in[9];
    const float* sh_v   = (const float*)d_in[10];
    const float* dep_W  = (const float*)d_in[11];
    const float* dep_g  = (const float*)d_in[12];
    const float* dep_b  = (const float*)d_in[13];
    const float* dep_m  = (const float*)d_in[14];
    const float* dep_v  = (const float*)d_in[15];
    const float* at_W   = (const float*)d_in[16];
    const float* at_g   = (const float*)d_in[17];
    const float* at_b   = (const float*)d_in[18];
    const float* at_m   = (const float*)d_in[19];
    const float* at_v   = (const float*)d_in[20];
    const float* Wout   = (const float*)d_in[21];

    int B = in_sizes[0] / 256;
    int grid = (B + TB - 1) / TB;
    size_t smem = (size_t)(TB * 256 * 3 + TB * 128 + TB * 64 * 2) * sizeof(float); // 192 KB

    cudaFuncSetAttribute(tabnet_fused, cudaFuncAttributeMaxDynamicSharedMemorySize, (int)smem);
    tabnet_fused<<<grid, NTH, smem>>>(inputs, in_g, in_b, in_m, in_v,
                                      sh_W0, sh_W1, sh_g, sh_b, sh_m, sh_v,
                                      dep_W, dep_g, dep_b, dep_m, dep_v,
                                      at_W, at_g, at_b, at_m, at_v,
                                      Wout, (float*)d_out, B);
}

// round 7
// speedup vs baseline: 1.0103x; 1.0103x over previous
#include <cuda_runtime.h>

// TabNet encoder, fully fused, packed f32x2 math.
// Weights staged through SMEM via cp.async (triple-buffered 8-k chunks):
//   - single weight fetch per CTA per chunk (kills 6x redundant L1 traffic)
//   - prefetch distance 2 chunks (~1500 cyc) >> L2 latency (234-262)
// One CTA = 48 rows, 384 threads (12 warps), 1 CTA/SM, prior in GMEM scratch.
// B=131072, D=256, UN=128 (2UN=256), ND=NA=64, NSTEPS=3.

#define TB 48            // rows per CTA
#define NTH 384          // threads per CTA
#define CK 8             // k-rows per weight chunk
#define NBUF 3           // chunk buffers
#define BMAX 131072

__device__ float g_prior[(size_t)BMAX * 256];

typedef unsigned long long u64;

__device__ __forceinline__ u64 dup2(float v) {
    u64 r; asm("mov.b64 %0,{%1,%1};" : "=l"(r) : "f"(v)); return r;
}
__device__ __forceinline__ void fma2_(u64& d, u64 a, u64 b) {
    asm("fma.rn.f32x2 %0,%1,%2,%3;" : "=l"(d) : "l"(a), "l"(b), "l"(d));
}
__device__ __forceinline__ float2 up2(u64 v) {
    float lo, hi; asm("mov.b64 {%0,%1},%2;" : "=f"(lo), "=f"(hi) : "l"(v));
    return make_float2(lo, hi);
}
__device__ __forceinline__ float sig_(float x) {
    return __fdividef(1.0f, 1.0f + __expf(-x));
}

__device__ __forceinline__ void cpa16(unsigned s, const void* g) {
    asm volatile("cp.async.cg.shared.global [%0], [%1], 16;" :: "r"(s), "l"(g));
}
__device__ __forceinline__ void cpa_commit() {
    asm volatile("cp.async.commit_group;" ::: "memory");
}
__device__ __forceinline__ void cpa_wait1() {
    asm volatile("cp.async.wait_group 1;" ::: "memory");
}

// issue cp.async for weight chunk c into buffer buf (CK*256 floats = 512 x 16B)
__device__ __forceinline__ void load_wchunk(const float* __restrict__ W, int c, int buf,
                                            unsigned wsm_base)
{
    const float* src = W + (size_t)c * (CK * 256);
    unsigned dst = wsm_base + buf * (CK * 256 * 4);
    int i = threadIdx.x;
    cpa16(dst + i * 16, src + i * 4);
    i += NTH;
    if (i < 512) cpa16(dst + i * 16, src + i * 4);
}

// H[TB][256] = BN(act[TB][AS..K] @ W[K][256]); thread tile 8 rows x 4 cols.
// cg = t&63 -> cols 4cg.., rg = t>>6 (0..5) -> rows 8rg..
// Weights flow GMEM -> (cp.async) -> wsm ring -> LDS.128.
template<int K, int AS>
__device__ __forceinline__ void gemm_bn256(
    const float* __restrict__ W,
    const float* __restrict__ gg, const float* __restrict__ bb,
    const float* __restrict__ mm, const float* __restrict__ vv,
    const float* act, float* H, float* wsm, unsigned wsm_base)
{
    const int t  = threadIdx.x;
    const int cg = t & 63;
    const int c0 = cg << 2;
    const int r0 = (t >> 6) << 3;
    const float* actb = act + r0 * AS;
    constexpr int NCH = K / CK;

    u64 acc[8][2];
#pragma unroll
    for (int r = 0; r < 8; r++) { acc[r][0] = 0ull; acc[r][1] = 0ull; }

    // prologue: chunks 0 and 1 in flight
    load_wchunk(W, 0, 0, wsm_base); cpa_commit();
    load_wchunk(W, 1, 1, wsm_base); cpa_commit();

#pragma unroll 1
    for (int c = 0; c < NCH; c++) {
        cpa_wait1();            // chunk c landed
        __syncthreads();        // visible to all; all done reading buf (c+2)%3
        if (c + 2 < NCH) load_wchunk(W, c + 2, (c + 2) % NBUF, wsm_base);
        cpa_commit();           // exactly one group per iteration (may be empty)

        const float* wb = wsm + (c % NBUF) * (CK * 256);
#pragma unroll
        for (int kk = 0; kk < CK; kk += 4) {
            ulonglong2 w[4];
#pragma unroll
            for (int i = 0; i < 4; i++)
                w[i] = *reinterpret_cast<const ulonglong2*>(wb + (kk + i) * 256 + c0);
#pragma unroll
            for (int rr = 0; rr < 8; rr++) {
                float4 a4 = *reinterpret_cast<const float4*>(actb + rr * AS + c * CK + kk);
                u64 ax = dup2(a4.x), ay = dup2(a4.y);
                u64 az = dup2(a4.z), aw = dup2(a4.w);
                fma2_(acc[rr][0], ax, w[0].x); fma2_(acc[rr][1], ax, w[0].y);
                fma2_(acc[rr][0], ay, w[1].x); fma2_(acc[rr][1], ay, w[1].y);
                fma2_(acc[rr][0], az, w[2].x); fma2_(acc[rr][1], az, w[2].y);
                fma2_(acc[rr][0], aw, w[3].x); fma2_(acc[rr][1], aw, w[3].y);
            }
        }
    }

    // folded-BN epilogue (vector param loads)
    float4 g4 = *reinterpret_cast<const float4*>(gg + c0);
    float4 b4 = *reinterpret_cast<const float4*>(bb + c0);
    float4 m4 = *reinterpret_cast<const float4*>(mm + c0);
    float4 v4 = *reinterpret_cast<const float4*>(vv + c0);
    float sc[4], bs[4];
    sc[0] = g4.x * rsqrtf(v4.x + 1e-3f); bs[0] = b4.x - m4.x * sc[0];
    sc[1] = g4.y * rsqrtf(v4.y + 1e-3f); bs[1] = b4.y - m4.y * sc[1];
    sc[2] = g4.z * rsqrtf(v4.z + 1e-3f); bs[2] = b4.z - m4.z * sc[2];
    sc[3] = g4.w * rsqrtf(v4.w + 1e-3f); bs[3] = b4.w - m4.w * sc[3];
#pragma unroll
    for (int rr = 0; rr < 8; rr++) {
        float2 lo = up2(acc[rr][0]), hi = up2(acc[rr][1]);
        float4 o;
        o.x = fmaf(lo.x, sc[0], bs[0]);
        o.y = fmaf(lo.y, sc[1], bs[1]);
        o.z = fmaf(hi.x, sc[2], bs[2]);
        o.w = fmaf(hi.y, sc[3], bs[3]);
        *reinterpret_cast<float4*>(H + (r0 + rr) * 256 + c0) = o;
    }
}

// GLU over H[TB][256]: out = H[:, :128] * sigmoid(H[:, 128:]).
__device__ __forceinline__ void glu_step(const float* H, float* outp, int os,
                                         const float* addp, int as_, bool combine)
{
    const int t = threadIdx.x;
    const int u = t & 127;
    const int q = t >> 7;                 // 0..2
#pragma unroll
    for (int r8 = 0; r8 < TB / 3; r8++) {
        int r = q * (TB / 3) + r8;
        float a = H[r * 256 + u];
        float b = H[r * 256 + 128 + u];
        float gl = a * sig_(b);
        if (combine) gl = 0.70710678118654752f * (addp[r * as_ + u] + gl);
        outp[r * os + u] = gl;
    }
}

template<int AS>
__device__ __forceinline__ void shared_block_(const float* act,
    const float* W0, const float* W1,
    const float* g, const float* b, const float* m, const float* v,
    float* X, float* H, float* G, float* wsm, unsigned wsm_base)
{
    __syncthreads();
    gemm_bn256<256, AS>(W0, g, b, m, v, act, H, wsm, wsm_base);
    __syncthreads();
    glu_step(H, G, 128, (const float*)0, 0, false);      // G = glu1
    __syncthreads();
    gemm_bn256<128, 128>(W1, g + 256, b + 256, m + 256, v + 256, G, H, wsm, wsm_base);
    __syncthreads();
    glu_step(H, X, 256, G, 128, true);                   // X[:, :128] = s*(glu1+glu2)
    __syncthreads();
}

__device__ __forceinline__ void dep_block_(const float* Wd, const float* g, const float* b,
    const float* m, const float* v, float* X, float* H, float* wsm, unsigned wsm_base)
{
#pragma unroll
    for (int i = 0; i < 2; i++) {
        __syncthreads();
        gemm_bn256<128, 256>(Wd + i * 128 * 256, g + i * 256, b + i * 256,
                             m + i * 256, v + i * 256, X, H, wsm, wsm_base);
        __syncthreads();
        glu_step(H, X, 256, X, 256, true);               // X = s*(X + glu)
    }
    __syncthreads();
}

__device__ __forceinline__ void post_dep_(const float* X, float* aB, float* agg, bool addagg)
{
#pragma unroll
    for (int i = 0; i < TB * 64 / NTH; i++) {
        int lin = threadIdx.x + NTH * i;
        int r = lin >> 6, c = lin & 63;
        aB[r * 64 + c] = X[r * 256 + 64 + c];
        if (addagg) agg[r * 64 + c] += fmaxf(X[r * 256 + c], 0.0f);
    }
    __syncthreads();
}

// z = prior * bn_logits (in H); sparsemax via Michelot projection; one warp = 4 rows.
// prior read from / written to GMEM scratch; step 0 uses implicit prior=1.
__device__ __forceinline__ void attn_sparsemax_(const float* H, const float* feat,
                                                float* X, long long rowbase, int B,
                                                int step)
{
    const int warp = threadIdx.x >> 5;     // 0..11
    const int lane = threadIdx.x & 31;
#pragma unroll
    for (int rr = 0; rr < TB / 12; rr++) {
        const int r = warp * (TB / 12) + rr;
        long long gr = rowbase + r; if (gr >= B) gr = B - 1;
        float* pp = g_prior + gr * 256;

        float pv[8], z[8];
#pragma unroll
        for (int i = 0; i < 8; i++) {
            int e = lane + 32 * i;
            pv[i] = (step == 0) ? 1.0f : pp[e];
            z[i] = pv[i] * H[r * 256 + e];
        }
        unsigned am = 0xFFu;
        float tau = 0.0f;
        for (int it = 0; it < 64; it++) {
            float s = 0.0f, cnt = 0.0f;
#pragma unroll
            for (int i = 0; i < 8; i++)
                if (am & (1u << i)) { s += z[i]; cnt += 1.0f; }
#pragma unroll
            for (int o = 16; o >= 1; o >>= 1) {
                s   += __shfl_xor_sync(0xffffffffu, s, o);
                cnt += __shfl_xor_sync(0xffffffffu, cnt, o);
            }
            tau = __fdividef(s - 1.0f, cnt);
            unsigned na = 0u;
#pragma unroll
            for (int i = 0; i < 8; i++)
                if (z[i] > tau) na |= (1u << i);
            int changed = (na != am);
            am = na;
            if (!__any_sync(0xffffffffu, changed)) break;
        }
#pragma unroll
        for (int i = 0; i < 8; i++) {
            int e = lane + 32 * i;
            float mv = fmaxf(z[i] - tau, 0.0f);
            X[r * 256 + e] = mv * feat[r * 256 + e];
            if (step < 2) pp[e] = pv[i] * (1.3f - mv);   // last step's prior unused
        }
    }
    __syncthreads();
}

__global__ void __launch_bounds__(NTH, 1)
tabnet_fused(const float* __restrict__ inputs,
             const float* __restrict__ in_g, const float* __restrict__ in_b,
             const float* __restrict__ in_m, const float* __restrict__ in_v,
             const float* __restrict__ sh_W0, const float* __restrict__ sh_W1,
             const float* __restrict__ sh_g, const float* __restrict__ sh_b,
             const float* __restrict__ sh_m, const float* __restrict__ sh_v,
             const float* __restrict__ dep_W, const float* __restrict__ dep_g,
             const float* __restrict__ dep_b, const float* __restrict__ dep_m,
             const float* __restrict__ dep_v,
             const float* __restrict__ at_W, const float* __restrict__ at_g,
             const float* __restrict__ at_b, const float* __restrict__ at_m,
             const float* __restrict__ at_v,
             const float* __restrict__ Wout,
             float* __restrict__ out, int B)
{
    extern __shared__ float sm_[];
    float* feat  = sm_;                 // [TB][256]
    float* X     = feat  + TB * 256;    // [TB][256]
    float* H     = X     + TB * 256;    // [TB][256]
    float* G     = H     + TB * 256;    // [TB][128]
    float* aB    = G     + TB * 128;    // [TB][64]
    float* agg   = aB    + TB * 64;     // [TB][64]
    float* wsm   = agg   + TB * 64;     // [NBUF][CK*256] weight ring
    unsigned wsm_base;
    {
        u64 gp = (u64)__cvta_generic_to_shared(wsm);
        wsm_base = (unsigned)gp;
    }

    const int t = threadIdx.x;
    const long long rowbase = (long long)blockIdx.x * TB;

    // input BN -> feat; agg = 0
    {
        const float4* in4 = reinterpret_cast<const float4*>(inputs);
        const float4* g4  = reinterpret_cast<const float4*>(in_g);
        const float4* b4  = reinterpret_cast<const float4*>(in_b);
        const float4* m4  = reinterpret_cast<const float4*>(in_m);
        const float4* v4  = reinterpret_cast<const float4*>(in_v);
#pragma unroll
        for (int i = 0; i < TB * 64 / NTH; i++) {
            int lin = t + NTH * i;           // float4 index
            int r = lin >> 6, d4 = lin & 63;
            long long gr = rowbase + r; if (gr >= B) gr = B - 1;
            float4 xv = in4[gr * 64 + d4];
            float4 gv = g4[d4], bv = b4[d4], mv = m4[d4], vv = v4[d4];
            float4 o; float s;
            s = gv.x * rsqrtf(vv.x + 1e-3f); o.x = fmaf(xv.x - mv.x, s, bv.x);
            s = gv.y * rsqrtf(vv.y + 1e-3f); o.y = fmaf(xv.y - mv.y, s, bv.y);
            s = gv.z * rsqrtf(vv.z + 1e-3f); o.z = fmaf(xv.z - mv.z, s, bv.z);
            s = gv.w * rsqrtf(vv.w + 1e-3f); o.w = fmaf(xv.w - mv.w, s, bv.w);
            reinterpret_cast<float4*>(feat)[lin] = o;
        }
#pragma unroll
        for (int i = 0; i < (TB * 16 + NTH - 1) / NTH; i++) {
            int lin = t + NTH * i;
            if (lin < TB * 16)
                reinterpret_cast<float4*>(agg)[lin] = make_float4(0.f, 0.f, 0.f, 0.f);
        }
    }
    __syncthreads();

    // initial shared + dep block (no agg accumulation)
    shared_block_<256>(feat, sh_W0, sh_W1, sh_g, sh_b, sh_m, sh_v, X, H, G, wsm, wsm_base);
    dep_block_(dep_W, dep_g, dep_b, dep_m, dep_v, X, H, wsm, wsm_base);
    post_dep_(X, aB, agg, false);

    // 3 decision steps
    for (int s = 0; s < 3; s++) {
        __syncthreads();
        gemm_bn256<64, 64>(at_W + s * 64 * 256, at_g + s * 256, at_b + s * 256,
                           at_m + s * 256, at_v + s * 256, aB, H, wsm, wsm_base);
        __syncthreads();
        attn_sparsemax_(H, feat, X, rowbase, B, s);   // X = mask * feat
        shared_block_<256>(X, sh_W0, sh_W1, sh_g, sh_b, sh_m, sh_v, X, H, G, wsm, wsm_base);
        dep_block_(dep_W + (s + 1) * 2 * 128 * 256,
                   dep_g + (s + 1) * 512, dep_b + (s + 1) * 512,
                   dep_m + (s + 1) * 512, dep_v + (s + 1) * 512, X, H, wsm, wsm_base);
        post_dep_(X, aB, agg, true);
    }

    // out = agg @ Wout  (64x64); rgx = t>>6 (0..5) -> 8 rows each
    {
        const int c   = t & 63;
        const int rgx = t >> 6;
        float acc[8];
#pragma unroll
        for (int rr = 0; rr < 8; rr++) acc[rr] = 0.0f;
        for (int k = 0; k < 64; k += 4) {
#pragma unroll
            for (int kk = 0; kk < 4; kk++) {
                float wv_ = Wout[(k + kk) * 64 + c];
#pragma unroll
                for (int rr = 0; rr < 8; rr++)
                    acc[rr] = fmaf(agg[(rgx * 8 + rr) * 64 + (k + kk)], wv_, acc[rr]);
            }
        }
#pragma unroll
        for (int rr = 0; rr < 8; rr++) {
            long long gr = rowbase + rgx * 8 + rr;
            if (gr < B) out[gr * 64 + c] = acc[rr];
        }
    }
}

extern "C" void kernel_launch(void* const* d_in, const int* in_sizes, int n_in,
                              void* d_out, int out_size)
{
    const float* inputs = (const float*)d_in[0];
    const float* in_g   = (const float*)d_in[1];
    const float* in_b   = (const float*)d_in[2];
    const float* in_m   = (const float*)d_in[3];
    const float* in_v   = (const float*)d_in[4];
    const float* sh_W0  = (const float*)d_in[5];
    const float* sh_W1  = (const float*)d_in[6];
    const float* sh_g   = (const float*)d_in[7];
    const float* sh_b   = (const float*)d_in[8];
    const float* sh_m   = (const float*)d_in[9];
    const float* sh_v   = (const float*)d_in[10];
    const float* dep_W  = (const float*)d_in[11];
    const float* dep_g  = (const float*)d_in[12];
    const float* dep_b  = (const float*)d_in[13];
    const float* dep_m  = (const float*)d_in[14];
    const float* dep_v  = (const float*)d_in[15];
    const float* at_W   = (const float*)d_in[16];
    const float* at_g   = (const float*)d_in[17];
    const float* at_b   = (const float*)d_in[18];
    const float* at_m   = (const float*)d_in[19];
    const float* at_v   = (const float*)d_in[20];
    const float* Wout   = (const float*)d_in[21];

    int B = in_sizes[0] / 256;
    int grid = (B + TB - 1) / TB;
    size_t smem = (size_t)(TB * 256 * 3 + TB * 128 + TB * 64 * 2 + NBUF * CK * 256)
                  * sizeof(float);   // 221184 B

    cudaFuncSetAttribute(tabnet_fused, cudaFuncAttributeMaxDynamicSharedMemorySize, (int)smem);
    tabnet_fused<<<grid, NTH, smem>>>(inputs, in_g, in_b, in_m, in_v,
                                      sh_W0, sh_W1, sh_g, sh_b, sh_m, sh_v,
                                      dep_W, dep_g, dep_b, dep_m, dep_v,
                                      at_W, at_g, at_b, at_m, at_v,
                                      Wout, (float*)d_out, B);
}

// round 8
// speedup vs baseline: 1.0109x; 1.0005x over previous
#include <cuda_runtime.h>

// TabNet encoder, fully fused, packed f32x2 math.
// Weights staged through SMEM via cp.async (triple-buffered 8-k chunks):
//   - single weight fetch per CTA per chunk (kills 6x redundant L1 traffic)
//   - prefetch distance 2 chunks (~1500 cyc) >> L2 latency (234-262)
// One CTA = 48 rows, 384 threads (12 warps), 1 CTA/SM, prior in GMEM scratch.
// B=131072, D=256, UN=128 (2UN=256), ND=NA=64, NSTEPS=3.

#define TB 48            // rows per CTA
#define NTH 384          // threads per CTA
#define CK 8             // k-rows per weight chunk
#define NBUF 3           // chunk buffers
#define BMAX 131072

__device__ float g_prior[(size_t)BMAX * 256];

typedef unsigned long long u64;

__device__ __forceinline__ u64 dup2(float v) {
    u64 r; asm("mov.b64 %0,{%1,%1};" : "=l"(r) : "f"(v)); return r;
}
__device__ __forceinline__ void fma2_(u64& d, u64 a, u64 b) {
    asm("fma.rn.f32x2 %0,%1,%2,%3;" : "=l"(d) : "l"(a), "l"(b), "l"(d));
}
__device__ __forceinline__ float2 up2(u64 v) {
    float lo, hi; asm("mov.b64 {%0,%1},%2;" : "=f"(lo), "=f"(hi) : "l"(v));
    return make_float2(lo, hi);
}
__device__ __forceinline__ float sig_(float x) {
    return __fdividef(1.0f, 1.0f + __expf(-x));
}

__device__ __forceinline__ void cpa16(unsigned s, const void* g) {
    asm volatile("cp.async.cg.shared.global [%0], [%1], 16;" :: "r"(s), "l"(g));
}
__device__ __forceinline__ void cpa_commit() {
    asm volatile("cp.async.commit_group;" ::: "memory");
}
__device__ __forceinline__ void cpa_wait1() {
    asm volatile("cp.async.wait_group 1;" ::: "memory");
}

// issue cp.async for weight chunk c into buffer buf (CK*256 floats = 512 x 16B)
__device__ __forceinline__ void load_wchunk(const float* __restrict__ W, int c, int buf,
                                            unsigned wsm_base)
{
    const float* src = W + (size_t)c * (CK * 256);
    unsigned dst = wsm_base + buf * (CK * 256 * 4);
    int i = threadIdx.x;
    cpa16(dst + i * 16, src + i * 4);
    i += NTH;
    if (i < 512) cpa16(dst + i * 16, src + i * 4);
}

// H[TB][256] = BN(act[TB][AS..K] @ W[K][256]); thread tile 8 rows x 4 cols.
// cg = t&63 -> cols 4cg.., rg = t>>6 (0..5) -> rows 8rg..
// Weights flow GMEM -> (cp.async) -> wsm ring -> LDS.128.
template<int K, int AS>
__device__ __forceinline__ void gemm_bn256(
    const float* __restrict__ W,
    const float* __restrict__ gg, const float* __restrict__ bb,
    const float* __restrict__ mm, const float* __restrict__ vv,
    const float* act, float* H, float* wsm, unsigned wsm_base)
{
    const int t  = threadIdx.x;
    const int cg = t & 63;
    const int c0 = cg << 2;
    const int r0 = (t >> 6) << 3;
    const float* actb = act + r0 * AS;
    constexpr int NCH = K / CK;

    u64 acc[8][2];
#pragma unroll
    for (int r = 0; r < 8; r++) { acc[r][0] = 0ull; acc[r][1] = 0ull; }

    // prologue: chunks 0 and 1 in flight
    load_wchunk(W, 0, 0, wsm_base); cpa_commit();
    load_wchunk(W, 1, 1, wsm_base); cpa_commit();

#pragma unroll 1
    for (int c = 0; c < NCH; c++) {
        cpa_wait1();            // chunk c landed
        __syncthreads();        // visible to all; all done reading buf (c+2)%3
        if (c + 2 < NCH) load_wchunk(W, c + 2, (c + 2) % NBUF, wsm_base);
        cpa_commit();           // exactly one group per iteration (may be empty)

        const float* wb = wsm + (c % NBUF) * (CK * 256);
#pragma unroll
        for (int kk = 0; kk < CK; kk += 4) {
            ulonglong2 w[4];
#pragma unroll
            for (int i = 0; i < 4; i++)
                w[i] = *reinterpret_cast<const ulonglong2*>(wb + (kk + i) * 256 + c0);
#pragma unroll
            for (int rr = 0; rr < 8; rr++) {
                float4 a4 = *reinterpret_cast<const float4*>(actb + rr * AS + c * CK + kk);
                u64 ax = dup2(a4.x), ay = dup2(a4.y);
                u64 az = dup2(a4.z), aw = dup2(a4.w);
                fma2_(acc[rr][0], ax, w[0].x); fma2_(acc[rr][1], ax, w[0].y);
                fma2_(acc[rr][0], ay, w[1].x); fma2_(acc[rr][1], ay, w[1].y);
                fma2_(acc[rr][0], az, w[2].x); fma2_(acc[rr][1], az, w[2].y);
                fma2_(acc[rr][0], aw, w[3].x); fma2_(acc[rr][1], aw, w[3].y);
            }
        }
    }

    // folded-BN epilogue (vector param loads)
    float4 g4 = *reinterpret_cast<const float4*>(gg + c0);
    float4 b4 = *reinterpret_cast<const float4*>(bb + c0);
    float4 m4 = *reinterpret_cast<const float4*>(mm + c0);
    float4 v4 = *reinterpret_cast<const float4*>(vv + c0);
    float sc[4], bs[4];
    sc[0] = g4.x * rsqrtf(v4.x + 1e-3f); bs[0] = b4.x - m4.x * sc[0];
    sc[1] = g4.y * rsqrtf(v4.y + 1e-3f); bs[1] = b4.y - m4.y * sc[1];
    sc[2] = g4.z * rsqrtf(v4.z + 1e-3f); bs[2] = b4.z - m4.z * sc[2];
    sc[3] = g4.w * rsqrtf(v4.w + 1e-3f); bs[3] = b4.w - m4.w * sc[3];
#pragma unroll
    for (int rr = 0; rr < 8; rr++) {
        float2 lo = up2(acc[rr][0]), hi = up2(acc[rr][1]);
        float4 o;
        o.x = fmaf(lo.x, sc[0], bs[0]);
        o.y = fmaf(lo.y, sc[1], bs[1]);
        o.z = fmaf(hi.x, sc[2], bs[2]);
        o.w = fmaf(hi.y, sc[3], bs[3]);
        *reinterpret_cast<float4*>(H + (r0 + rr) * 256 + c0) = o;
    }
}

// GLU over H[TB][256]: out = H[:, :128] * sigmoid(H[:, 128:]).
__device__ __forceinline__ void glu_step(const float* H, float* outp, int os,
                                         const float* addp, int as_, bool combine)
{
    const int t = threadIdx.x;
    const int u = t & 127;
    const int q = t >> 7;                 // 0..2
#pragma unroll
    for (int r8 = 0; r8 < TB / 3; r8++) {
        int r = q * (TB / 3) + r8;
        float a = H[r * 256 + u];
        float b = H[r * 256 + 128 + u];
        float gl = a * sig_(b);
        if (combine) gl = 0.70710678118654752f * (addp[r * as_ + u] + gl);
        outp[r * os + u] = gl;
    }
}

template<int AS>
__device__ __forceinline__ void shared_block_(const float* act,
    const float* W0, const float* W1,
    const float* g, const float* b, const float* m, const float* v,
    float* X, float* H, float* G, float* wsm, unsigned wsm_base)
{
    __syncthreads();
    gemm_bn256<256, AS>(W0, g, b, m, v, act, H, wsm, wsm_base);
    __syncthreads();
    glu_step(H, G, 128, (const float*)0, 0, false);      // G = glu1
    __syncthreads();
    gemm_bn256<128, 128>(W1, g + 256, b + 256, m + 256, v + 256, G, H, wsm, wsm_base);
    __syncthreads();
    glu_step(H, X, 256, G, 128, true);                   // X[:, :128] = s*(glu1+glu2)
    __syncthreads();
}

__device__ __forceinline__ void dep_block_(const float* Wd, const float* g, const float* b,
    const float* m, const float* v, float* X, float* H, float* wsm, unsigned wsm_base)
{
#pragma unroll
    for (int i = 0; i < 2; i++) {
        __syncthreads();
        gemm_bn256<128, 256>(Wd + i * 128 * 256, g + i * 256, b + i * 256,
                             m + i * 256, v + i * 256, X, H, wsm, wsm_base);
        __syncthreads();
        glu_step(H, X, 256, X, 256, true);               // X = s*(X + glu)
    }
    __syncthreads();
}

__device__ __forceinline__ void post_dep_(const float* X, float* aB, float* agg, bool addagg)
{
#pragma unroll
    for (int i = 0; i < TB * 64 / NTH; i++) {
        int lin = threadIdx.x + NTH * i;
        int r = lin >> 6, c = lin & 63;
        aB[r * 64 + c] = X[r * 256 + 64 + c];
        if (addagg) agg[r * 64 + c] += fmaxf(X[r * 256 + c], 0.0f);
    }
    __syncthreads();
}

// z = prior * bn_logits (in H); sparsemax via Michelot projection; one warp = 4 rows.
// prior read from / written to GMEM scratch; step 0 uses implicit prior=1.
__device__ __forceinline__ void attn_sparsemax_(const float* H, const float* feat,
                                                float* X, long long rowbase, int B,
                                                int step)
{
    const int warp = threadIdx.x >> 5;     // 0..11
    const int lane = threadIdx.x & 31;
#pragma unroll
    for (int rr = 0; rr < TB / 12; rr++) {
        const int r = warp * (TB / 12) + rr;
        long long gr = rowbase + r; if (gr >= B) gr = B - 1;
        float* pp = g_prior + gr * 256;

        float pv[8], z[8];
#pragma unroll
        for (int i = 0; i < 8; i++) {
            int e = lane + 32 * i;
            pv[i] = (step == 0) ? 1.0f : pp[e];
            z[i] = pv[i] * H[r * 256 + e];
        }
        unsigned am = 0xFFu;
        float tau = 0.0f;
        for (int it = 0; it < 64; it++) {
            float s = 0.0f, cnt = 0.0f;
#pragma unroll
            for (int i = 0; i < 8; i++)
                if (am & (1u << i)) { s += z[i]; cnt += 1.0f; }
#pragma unroll
            for (int o = 16; o >= 1; o >>= 1) {
                s   += __shfl_xor_sync(0xffffffffu, s, o);
                cnt += __shfl_xor_sync(0xffffffffu, cnt, o);
            }
            tau = __fdividef(s - 1.0f, cnt);
            unsigned na = 0u;
#pragma unroll
            for (int i = 0; i < 8; i++)
                if (z[i] > tau) na |= (1u << i);
            int changed = (na != am);
            am = na;
            if (!__any_sync(0xffffffffu, changed)) break;
        }
#pragma unroll
        for (int i = 0; i < 8; i++) {
            int e = lane + 32 * i;
            float mv = fmaxf(z[i] - tau, 0.0f);
            X[r * 256 + e] = mv * feat[r * 256 + e];
            if (step < 2) pp[e] = pv[i] * (1.3f - mv);   // last step's prior unused
        }
    }
    __syncthreads();
}

__global__ void __launch_bounds__(NTH, 1)
tabnet_fused(const float* __restrict__ inputs,
             const float* __restrict__ in_g, const float* __restrict__ in_b,
             const float* __restrict__ in_m, const float* __restrict__ in_v,
             const float* __restrict__ sh_W0, const float* __restrict__ sh_W1,
             const float* __restrict__ sh_g, const float* __restrict__ sh_b,
             const float* __restrict__ sh_m, const float* __restrict__ sh_v,
             const float* __restrict__ dep_W, const float* __restrict__ dep_g,
             const float* __restrict__ dep_b, const float* __restrict__ dep_m,
             const float* __restrict__ dep_v,
             const float* __restrict__ at_W, const float* __restrict__ at_g,
             const float* __restrict__ at_b, const float* __restrict__ at_m,
             const float* __restrict__ at_v,
             const float* __restrict__ Wout,
             float* __restrict__ out, int B)
{
    extern __shared__ float sm_[];
    float* feat  = sm_;                 // [TB][256]
    float* X     = feat  + TB * 256;    // [TB][256]
    float* H     = X     + TB * 256;    // [TB][256]
    float* G     = H     + TB * 256;    // [TB][128]
    float* aB    = G     + TB * 128;    // [TB][64]
    float* agg   = aB    + TB * 64;     // [TB][64]
    float* wsm   = agg   + TB * 64;     // [NBUF][CK*256] weight ring
    unsigned wsm_base;
    {
        u64 gp = (u64)__cvta_generic_to_shared(wsm);
        wsm_base = (unsigned)gp;
    }

    const int t = threadIdx.x;
    const long long rowbase = (long long)blockIdx.x * TB;

    // input BN -> feat; agg = 0
    {
        const float4* in4 = reinterpret_cast<const float4*>(inputs);
        const float4* g4  = reinterpret_cast<const float4*>(in_g);
        const float4* b4  = reinterpret_cast<const float4*>(in_b);
        const float4* m4  = reinterpret_cast<const float4*>(in_m);
        const float4* v4  = reinterpret_cast<const float4*>(in_v);
#pragma unroll
        for (int i = 0; i < TB * 64 / NTH; i++) {
            int lin = t + NTH * i;           // float4 index
            int r = lin >> 6, d4 = lin & 63;
            long long gr = rowbase + r; if (gr >= B) gr = B - 1;
            float4 xv = in4[gr * 64 + d4];
            float4 gv = g4[d4], bv = b4[d4], mv = m4[d4], vv = v4[d4];
            float4 o; float s;
            s = gv.x * rsqrtf(vv.x + 1e-3f); o.x = fmaf(xv.x - mv.x, s, bv.x);
            s = gv.y * rsqrtf(vv.y + 1e-3f); o.y = fmaf(xv.y - mv.y, s, bv.y);
            s = gv.z * rsqrtf(vv.z + 1e-3f); o.z = fmaf(xv.z - mv.z, s, bv.z);
            s = gv.w * rsqrtf(vv.w + 1e-3f); o.w = fmaf(xv.w - mv.w, s, bv.w);
            reinterpret_cast<float4*>(feat)[lin] = o;
        }
#pragma unroll
        for (int i = 0; i < (TB * 16 + NTH - 1) / NTH; i++) {
            int lin = t + NTH * i;
            if (lin < TB * 16)
                reinterpret_cast<float4*>(agg)[lin] = make_float4(0.f, 0.f, 0.f, 0.f);
        }
    }
    __syncthreads();

    // initial shared + dep block (no agg accumulation)
    shared_block_<256>(feat, sh_W0, sh_W1, sh_g, sh_b, sh_m, sh_v, X, H, G, wsm, wsm_base);
    dep_block_(dep_W, dep_g, dep_b, dep_m, dep_v, X, H, wsm, wsm_base);
    post_dep_(X, aB, agg, false);

    // 3 decision steps
    for (int s = 0; s < 3; s++) {
        __syncthreads();
        gemm_bn256<64, 64>(at_W + s * 64 * 256, at_g + s * 256, at_b + s * 256,
                           at_m + s * 256, at_v + s * 256, aB, H, wsm, wsm_base);
        __syncthreads();
        attn_sparsemax_(H, feat, X, rowbase, B, s);   // X = mask * feat
        shared_block_<256>(X, sh_W0, sh_W1, sh_g, sh_b, sh_m, sh_v, X, H, G, wsm, wsm_base);
        dep_block_(dep_W + (s + 1) * 2 * 128 * 256,
                   dep_g + (s + 1) * 512, dep_b + (s + 1) * 512,
                   dep_m + (s + 1) * 512, dep_v + (s + 1) * 512, X, H, wsm, wsm_base);
        post_dep_(X, aB, agg, true);
    }

    // out = agg @ Wout  (64x64); rgx = t>>6 (0..5) -> 8 rows each
    {
        const int c   = t & 63;
        const int rgx = t >> 6;
        float acc[8];
#pragma unroll
        for (int rr = 0; rr < 8; rr++) acc[rr] = 0.0f;
        for (int k = 0; k < 64; k += 4) {
#pragma unroll
            for (int kk = 0; kk < 4; kk++) {
                float wv_ = Wout[(k + kk) * 64 + c];
#pragma unroll
                for (int rr = 0; rr < 8; rr++)
                    acc[rr] = fmaf(agg[(rgx * 8 + rr) * 64 + (k + kk)], wv_, acc[rr]);
            }
        }
#pragma unroll
        for (int rr = 0; rr < 8; rr++) {
            long long gr = rowbase + rgx * 8 + rr;
            if (gr < B) out[gr * 64 + c] = acc[rr];
        }
    }
}

extern "C" void kernel_launch(void* const* d_in, const int* in_sizes, int n_in,
                              void* d_out, int out_size)
{
    const float* inputs = (const float*)d_in[0];
    const float* in_g   = (const float*)d_in[1];
    const float* in_b   = (const float*)d_in[2];
    const float* in_m   = (const float*)d_in[3];
    const float* in_v   = (const float*)d_in[4];
    const float* sh_W0  = (const float*)d_in[5];
    const float* sh_W1  = (const float*)d_in[6];
    const float* sh_g   = (const float*)d_in[7];
    const float* sh_b   = (const float*)d_in[8];
    const float* sh_m   = (const float*)d_in[9];
    const float* sh_v   = (const float*)d_in[10];
    const float* dep_W  = (const float*)d_in[11];
    const float* dep_g  = (const float*)d_in[12];
    const float* dep_b  = (const float*)d_in[13];
    const float* dep_m  = (const float*)d_in[14];
    const float* dep_v  = (const float*)d_in[15];
    const float* at_W   = (const float*)d_in[16];
    const float* at_g   = (const float*)d_in[17];
    const float* at_b   = (const float*)d_in[18];
    const float* at_m   = (const float*)d_in[19];
    const float* at_v   = (const float*)d_in[20];
    const float* Wout   = (const float*)d_in[21];

    int B = in_sizes[0] / 256;
    int grid = (B + TB - 1) / TB;
    size_t smem = (size_t)(TB * 256 * 3 + TB * 128 + TB * 64 * 2 + NBUF * CK * 256)
                  * sizeof(float);   // 221184 B

    cudaFuncSetAttribute(tabnet_fused, cudaFuncAttributeMaxDynamicSharedMemorySize, (int)smem);
    tabnet_fused<<<grid, NTH, smem>>>(inputs, in_g, in_b, in_m, in_v,
                                      sh_W0, sh_W1, sh_g, sh_b, sh_m, sh_v,
                                      dep_W, dep_g, dep_b, dep_m, dep_v,
                                      at_W, at_g, at_b, at_m, at_v,
                                      Wout, (float*)d_out, B);
}

// round 9
// speedup vs baseline: 1.9375x; 1.9167x over previous
#include <cuda_runtime.h>
#include <cuda_bf16.h>

// TabNet encoder on tensor cores: bf16 hi/lo split mma.sync (3-term compensated).
// CTA = 64 rows, 256 threads (8 warps). Warp n-tiles pair cols c and c+128 so
// GLU is lane-local. Weights pre-split to bf16 planes, BN pre-folded (prep kernel).
// B=131072, D=256, UN=128, ND=NA=64, NSTEPS=3.

#define TB 64
#define NTH 256
#define CK 32
#define W_ROWS 1600
#define BMAX 131072

#define WROW_SH0 0
#define WROW_SH1 256
#define WROW_DEP 384
#define WROW_AT  1408

__device__ __nv_bfloat16 g_whi[W_ROWS * 256];
__device__ __nv_bfloat16 g_wlo[W_ROWS * 256];
__device__ float2 g_fold[14 * 256];
__device__ float g_prior[(size_t)BMAX * 256];

// smem layout (bytes)
#define OFF_MPH 0          // 64 x 264 bf16
#define OFF_MPL 33792
#define OFF_GPH 67584      // 64 x 136 bf16
#define OFF_GPL 84992
#define OFF_XPH 102400
#define OFF_XPL 119808
#define OFF_AGG 137216     // 64 x 64 f32
#define OFF_RING 153600    // 2 bufs x 2 planes x 32x264 bf16
#define SMEM_TOTAL 221184

__device__ __forceinline__ float sig_(float x) {
    return __fdividef(1.0f, 1.0f + __expf(-x));
}
__device__ __forceinline__ unsigned sptr(const void* p) {
    return (unsigned)__cvta_generic_to_shared(p);
}
__device__ __forceinline__ void cpa16(unsigned s, const void* g) {
    asm volatile("cp.async.cg.shared.global [%0], [%1], 16;" :: "r"(s), "l"(g));
}
__device__ __forceinline__ void cpa_commit() {
    asm volatile("cp.async.commit_group;" ::: "memory");
}
__device__ __forceinline__ void cpa_wait1() {
    asm volatile("cp.async.wait_group 1;" ::: "memory");
}
__device__ __forceinline__ void ldm4(unsigned a, unsigned& r0, unsigned& r1,
                                     unsigned& r2, unsigned& r3) {
    asm volatile("ldmatrix.sync.aligned.m8n8.x4.shared.b16 {%0,%1,%2,%3},[%4];"
                 : "=r"(r0), "=r"(r1), "=r"(r2), "=r"(r3) : "r"(a));
}
__device__ __forceinline__ void ldm4t(unsigned a, unsigned& r0, unsigned& r1,
                                      unsigned& r2, unsigned& r3) {
    asm volatile("ldmatrix.sync.aligned.m8n8.x4.trans.shared.b16 {%0,%1,%2,%3},[%4];"
                 : "=r"(r0), "=r"(r1), "=r"(r2), "=r"(r3) : "r"(a));
}
__device__ __forceinline__ void mma_bf16(float* d, const unsigned* a, const unsigned* b) {
    asm volatile("mma.sync.aligned.m16n8k16.row.col.f32.bf16.bf16.f32 "
                 "{%0,%1,%2,%3},{%4,%5,%6,%7},{%8,%9},{%0,%1,%2,%3};"
                 : "+f"(d[0]), "+f"(d[1]), "+f"(d[2]), "+f"(d[3])
                 : "r"(a[0]), "r"(a[1]), "r"(a[2]), "r"(a[3]), "r"(b[0]), "r"(b[1]));
}
__device__ __forceinline__ void sts32(unsigned a, unsigned v) {
    asm volatile("st.shared.b32 [%0],%1;" :: "r"(a), "r"(v));
}
__device__ __forceinline__ unsigned lds32(unsigned a) {
    unsigned v; asm volatile("ld.shared.b32 %0,[%1];" : "=r"(v) : "r"(a)); return v;
}
__device__ __forceinline__ void sts16(unsigned a, unsigned short v) {
    asm volatile("st.shared.u16 [%0],%1;" :: "r"(a), "h"(v));
}
__device__ __forceinline__ unsigned short lds16(unsigned a) {
    unsigned short v; asm volatile("ld.shared.u16 %0,[%1];" : "=h"(v) : "r"(a)); return v;
}
__device__ __forceinline__ float bfu(unsigned short u) {
    return __bfloat162float(__ushort_as_bfloat16(u));
}
__device__ __forceinline__ void packsplit(float a, float b, unsigned& hi, unsigned& lo) {
    __nv_bfloat16 ah = __float2bfloat16(a), bh = __float2bfloat16(b);
    float la = a - __bfloat162float(ah), lb = b - __bfloat162float(bh);
    hi = (unsigned)__bfloat16_as_ushort(ah) | ((unsigned)__bfloat16_as_ushort(bh) << 16);
    lo = (unsigned)__bfloat16_as_ushort(__float2bfloat16(la))
       | ((unsigned)__bfloat16_as_ushort(__float2bfloat16(lb)) << 16);
}
__device__ __forceinline__ float2 up_pair(unsigned h, unsigned l) {
    return make_float2(bfu((unsigned short)(h & 0xFFFF)) + bfu((unsigned short)(l & 0xFFFF)),
                       bfu((unsigned short)(h >> 16)) + bfu((unsigned short)(l >> 16)));
}

// ---- prep: split weights to bf16 hi/lo planes; fold BN to (scale,bias) ----
__global__ void prep_kernel(const float* __restrict__ sh_W0, const float* __restrict__ sh_W1,
    const float* __restrict__ dep_W, const float* __restrict__ at_W,
    const float* __restrict__ in_g, const float* __restrict__ in_b,
    const float* __restrict__ in_m, const float* __restrict__ in_v,
    const float* __restrict__ sh_g, const float* __restrict__ sh_b,
    const float* __restrict__ sh_m, const float* __restrict__ sh_v,
    const float* __restrict__ dep_g, const float* __restrict__ dep_b,
    const float* __restrict__ dep_m, const float* __restrict__ dep_v,
    const float* __restrict__ at_g, const float* __restrict__ at_b,
    const float* __restrict__ at_m, const float* __restrict__ at_v)
{
    int tid = blockIdx.x * blockDim.x + threadIdx.x;
    int nthr = gridDim.x * blockDim.x;
    for (int i = tid; i < W_ROWS * 256; i += nthr) {
        int row = i >> 8;
        float w;
        if (row < 256)       w = sh_W0[i];
        else if (row < 384)  w = sh_W1[i - 256 * 256];
        else if (row < 1408) w = dep_W[i - 384 * 256];
        else                 w = at_W[i - 1408 * 256];
        __nv_bfloat16 hi = __float2bfloat16(w);
        g_whi[i] = hi;
        g_wlo[i] = __float2bfloat16(w - __bfloat162float(hi));
    }
    for (int i = tid; i < 14 * 256; i += nthr) {
        int l = i >> 8, c = i & 255;
        float g, b, m, v;
        if (l == 0)       { g = in_g[c]; b = in_b[c]; m = in_m[c]; v = in_v[c]; }
        else if (l <= 2)  { int j = (l - 1) * 256 + c;  g = sh_g[j];  b = sh_b[j];  m = sh_m[j];  v = sh_v[j]; }
        else if (l <= 10) { int j = (l - 3) * 256 + c;  g = dep_g[j]; b = dep_b[j]; m = dep_m[j]; v = dep_v[j]; }
        else              { int j = (l - 11) * 256 + c; g = at_g[j];  b = at_b[j];  m = at_m[j];  v = at_v[j]; }
        float sc = g * rsqrtf(v + 1e-3f);
        g_fold[i] = make_float2(sc, b - m * sc);
    }
}

// ---- GEMM core: 64 x 256 = A(64xK) @ W(Kx256), bf16 split, ring-buffered ----
__device__ __forceinline__ void load_wchunk(int row0, int buf, unsigned ring_s) {
    int t = threadIdx.x;
#pragma unroll
    for (int q = 0; q < 8; q++) {
        int idx = t + NTH * q;               // 0..2047
        int plane = idx >> 10;
        int rem = idx & 1023;
        int row = rem >> 5, seg = rem & 31;
        const __nv_bfloat16* src = (plane ? g_wlo : g_whi) + (row0 + row) * 256 + seg * 8;
        cpa16(ring_s + buf * 33792 + plane * 16896 + (row * 264 + seg * 8) * 2, src);
    }
}

template<int K>
__device__ __forceinline__ void gemm_core(unsigned a_hi, unsigned a_lo, int strideA,
                                          int wrow0, unsigned ring_s, float (&acc)[4][4][4])
{
    const int lane = threadIdx.x & 31;
    const int w = threadIdx.x >> 5;
    const int l15 = lane & 15;
    const int h8 = (lane >> 4) << 3;
#pragma unroll
    for (int m = 0; m < 4; m++)
#pragma unroll
        for (int n = 0; n < 4; n++)
#pragma unroll
            for (int e = 0; e < 4; e++) acc[m][n][e] = 0.f;

    constexpr int NCH = K / CK;
    load_wchunk(wrow0, 0, ring_s);
    cpa_commit();

#pragma unroll 1
    for (int c = 0; c < NCH; c++) {
        if (c + 1 < NCH) load_wchunk(wrow0 + (c + 1) * CK, (c + 1) & 1, ring_s);
        cpa_commit();
        cpa_wait1();
        __syncthreads();
        unsigned wbh = ring_s + (c & 1) * 33792;
        unsigned wbl = wbh + 16896;
#pragma unroll
        for (int ks = 0; ks < CK / 16; ks++) {
            int k0 = ks * 16;
            unsigned bh[4][2], bl[4][2];
            unsigned boff = (unsigned)(((k0 + l15) * 264 + 16 * w + h8) * 2);
            ldm4t(wbh + boff, bh[0][0], bh[0][1], bh[1][0], bh[1][1]);
            ldm4t(wbh + boff + 256, bh[2][0], bh[2][1], bh[3][0], bh[3][1]);
            ldm4t(wbl + boff, bl[0][0], bl[0][1], bl[1][0], bl[1][1]);
            ldm4t(wbl + boff + 256, bl[2][0], bl[2][1], bl[3][0], bl[3][1]);
#pragma unroll
            for (int m = 0; m < 4; m++) {
                unsigned aoff = (unsigned)(((m * 16 + l15) * strideA + c * CK + k0 + h8) * 2);
                unsigned ah[4], al[4];
                ldm4(a_hi + aoff, ah[0], ah[1], ah[2], ah[3]);
                ldm4(a_lo + aoff, al[0], al[1], al[2], al[3]);
#pragma unroll
                for (int nt = 0; nt < 4; nt++) {
                    mma_bf16(acc[m][nt], ah, bh[nt]);
                    mma_bf16(acc[m][nt], al, bh[nt]);
                    mma_bf16(acc[m][nt], ah, bl[nt]);
                }
            }
        }
        __syncthreads();
    }
}

// ---- epilogues ----
// MODE 0: GLU1 -> G planes.  MODE 1: X = s*(G + GLU2) -> X planes.
// MODE 2: X = s*(X + GLU) in place (+ optional agg += relu(X[:, :64])).
template<int MODE>
__device__ __forceinline__ void epi_glu(float (&acc)[4][4][4], int layer,
                                        unsigned gp_hi, unsigned gp_lo,
                                        unsigned xp_hi, unsigned xp_lo,
                                        float* agg, bool addagg)
{
    const int lane = threadIdx.x & 31;
    const int w = threadIdx.x >> 5;
    const int tig = lane & 3, gid = lane >> 2;
    float2 fa[2][2], fb[2][2];
#pragma unroll
    for (int j = 0; j < 2; j++)
#pragma unroll
        for (int e = 0; e < 2; e++) {
            int cc = 16 * w + 8 * j + 2 * tig + e;
            fa[j][e] = g_fold[layer * 256 + cc];
            fb[j][e] = g_fold[layer * 256 + cc + 128];
        }
#pragma unroll
    for (int m = 0; m < 4; m++)
#pragma unroll
        for (int j = 0; j < 2; j++)
#pragma unroll
            for (int hh = 0; hh < 2; hh++) {
                int r = m * 16 + gid + 8 * hh;
                int u0 = 16 * w + 8 * j + 2 * tig;
                float v[2];
#pragma unroll
                for (int e = 0; e < 2; e++) {
                    float ha = fmaf(acc[m][j][hh * 2 + e], fa[j][e].x, fa[j][e].y);
                    float hb = fmaf(acc[m][j + 2][hh * 2 + e], fb[j][e].x, fb[j][e].y);
                    v[e] = ha * sig_(hb);
                }
                unsigned dsth = ((MODE == 0) ? gp_hi : xp_hi) + (r * 136 + u0) * 2;
                unsigned dstl = ((MODE == 0) ? gp_lo : xp_lo) + (r * 136 + u0) * 2;
                if (MODE == 1) {
                    float2 g = up_pair(lds32(gp_hi + (r * 136 + u0) * 2),
                                       lds32(gp_lo + (r * 136 + u0) * 2));
                    v[0] = 0.70710678118654752f * (g.x + v[0]);
                    v[1] = 0.70710678118654752f * (g.y + v[1]);
                } else if (MODE == 2) {
                    float2 x = up_pair(lds32(dsth), lds32(dstl));
                    v[0] = 0.70710678118654752f * (x.x + v[0]);
                    v[1] = 0.70710678118654752f * (x.y + v[1]);
                    if (addagg && u0 < 64) {
                        agg[r * 64 + u0]     += fmaxf(v[0], 0.f);
                        agg[r * 64 + u0 + 1] += fmaxf(v[1], 0.f);
                    }
                }
                unsigned ph, pl;
                packsplit(v[0], v[1], ph, pl);
                sts32(dsth, ph);
                sts32(dstl, pl);
            }
}

// logits: BN'd accumulator -> MP planes (all 256 cols, stride 264)
__device__ __forceinline__ void epi_logits(float (&acc)[4][4][4], int layer,
                                           unsigned mp_hi, unsigned mp_lo)
{
    const int lane = threadIdx.x & 31;
    const int w = threadIdx.x >> 5;
    const int tig = lane & 3, gid = lane >> 2;
#pragma unroll
    for (int m = 0; m < 4; m++)
#pragma unroll
        for (int nt = 0; nt < 4; nt++) {
            int cn = (nt < 2) ? (16 * w + 8 * nt) : (128 + 16 * w + 8 * (nt - 2));
            int u0 = cn + 2 * tig;
            float2 f0 = g_fold[layer * 256 + u0];
            float2 f1 = g_fold[layer * 256 + u0 + 1];
#pragma unroll
            for (int hh = 0; hh < 2; hh++) {
                int r = m * 16 + gid + 8 * hh;
                float v0 = fmaf(acc[m][nt][hh * 2 + 0], f0.x, f0.y);
                float v1 = fmaf(acc[m][nt][hh * 2 + 1], f1.x, f1.y);
                unsigned ph, pl;
                packsplit(v0, v1, ph, pl);
                sts32(mp_hi + (r * 264 + u0) * 2, ph);
                sts32(mp_lo + (r * 264 + u0) * 2, pl);
            }
        }
}

// sparsemax: z = prior * logits(MP); Michelot; MP <- mask * feat(inputs)
__device__ __forceinline__ void sparsemax_phase(int step, long long rowbase, int B,
                                                unsigned mp_hi, unsigned mp_lo,
                                                const float* __restrict__ inputs)
{
    const int w = threadIdx.x >> 5;
    const int lane = threadIdx.x & 31;
    float2 fin[8];
#pragma unroll
    for (int i = 0; i < 8; i++) fin[i] = g_fold[lane + 32 * i];

#pragma unroll 1
    for (int rr = 0; rr < 8; rr++) {
        int r = w * 8 + rr;
        long long gr = rowbase + r; if (gr >= B) gr = B - 1;
        float* pp = g_prior + gr * 256;
        const float* xin = inputs + gr * 256;

        float pv[8], z[8];
#pragma unroll
        for (int i = 0; i < 8; i++) {
            int e = lane + 32 * i;
            float lg = bfu(lds16(mp_hi + (r * 264 + e) * 2))
                     + bfu(lds16(mp_lo + (r * 264 + e) * 2));
            pv[i] = (step == 0) ? 1.0f : pp[e];
            z[i] = pv[i] * lg;
        }
        unsigned am = 0xFFu;
        float tau = 0.0f;
        for (int it = 0; it < 64; it++) {
            float s = 0.0f, cnt = 0.0f;
#pragma unroll
            for (int i = 0; i < 8; i++)
                if (am & (1u << i)) { s += z[i]; cnt += 1.0f; }
#pragma unroll
            for (int o = 16; o >= 1; o >>= 1) {
                s   += __shfl_xor_sync(0xffffffffu, s, o);
                cnt += __shfl_xor_sync(0xffffffffu, cnt, o);
            }
            tau = __fdividef(s - 1.0f, cnt);
            unsigned na = 0u;
#pragma unroll
            for (int i = 0; i < 8; i++)
                if (z[i] > tau) na |= (1u << i);
            int changed = (na != am);
            am = na;
            if (!__any_sync(0xffffffffu, changed)) break;
        }
#pragma unroll
        for (int i = 0; i < 8; i++) {
            int e = lane + 32 * i;
            float mv = fmaxf(z[i] - tau, 0.0f);
            float feat = fmaf(fin[i].x, xin[e], fin[i].y);
            float o = mv * feat;
            __nv_bfloat16 oh = __float2bfloat16(o);
            sts16(mp_hi + (r * 264 + e) * 2, __bfloat16_as_ushort(oh));
            sts16(mp_lo + (r * 264 + e) * 2,
                  __bfloat16_as_ushort(__float2bfloat16(o - __bfloat162float(oh))));
            if (step < 2) pp[e] = pv[i] * (1.3f - mv);
        }
    }
}

__global__ void __launch_bounds__(NTH, 1)
tabnet_mma(const float* __restrict__ inputs, const float* __restrict__ Wout,
           float* __restrict__ out, int B)
{
    extern __shared__ char sm[];
    const unsigned mp_hi = sptr(sm + OFF_MPH), mp_lo = sptr(sm + OFF_MPL);
    const unsigned gp_hi = sptr(sm + OFF_GPH), gp_lo = sptr(sm + OFF_GPL);
    const unsigned xp_hi = sptr(sm + OFF_XPH), xp_lo = sptr(sm + OFF_XPL);
    float* agg = reinterpret_cast<float*>(sm + OFF_AGG);
    const unsigned ring_s = sptr(sm + OFF_RING);

    const int t = threadIdx.x;
    const long long rowbase = (long long)blockIdx.x * TB;

    // phase 0: feat = BN(input) -> MP planes; agg = 0
    {
        const float4* in4 = reinterpret_cast<const float4*>(inputs);
#pragma unroll
        for (int i = 0; i < 16; i++) {
            int lin = t + NTH * i;           // float4 index over 64 x 64
            int r = lin >> 6, c4 = lin & 63;
            long long gr = rowbase + r; if (gr >= B) gr = B - 1;
            float4 xv = in4[gr * 64 + c4];
            float2 f0 = g_fold[c4 * 4 + 0], f1 = g_fold[c4 * 4 + 1];
            float2 f2 = g_fold[c4 * 4 + 2], f3 = g_fold[c4 * 4 + 3];
            unsigned h01, l01, h23, l23;
            packsplit(fmaf(f0.x, xv.x, f0.y), fmaf(f1.x, xv.y, f1.y), h01, l01);
            packsplit(fmaf(f2.x, xv.z, f2.y), fmaf(f3.x, xv.w, f3.y), h23, l23);
            unsigned base = (unsigned)((r * 264 + c4 * 4) * 2);
            sts32(mp_hi + base, h01); sts32(mp_hi + base + 4, h23);
            sts32(mp_lo + base, l01); sts32(mp_lo + base + 4, l23);
        }
        float4* a4 = reinterpret_cast<float4*>(agg);
#pragma unroll
        for (int i = 0; i < 4; i++)
            a4[t + NTH * i] = make_float4(0.f, 0.f, 0.f, 0.f);
    }
    __syncthreads();

    float acc[4][4][4];

    // initial shared block + dep block
    gemm_core<256>(mp_hi, mp_lo, 264, WROW_SH0, ring_s, acc);
    epi_glu<0>(acc, 1, gp_hi, gp_lo, xp_hi, xp_lo, agg, false);
    __syncthreads();
    gemm_core<128>(gp_hi, gp_lo, 136, WROW_SH1, ring_s, acc);
    epi_glu<1>(acc, 2, gp_hi, gp_lo, xp_hi, xp_lo, agg, false);
    __syncthreads();
#pragma unroll 1
    for (int i = 0; i < 2; i++) {
        gemm_core<128>(xp_hi, xp_lo, 136, WROW_DEP + i * 128, ring_s, acc);
        epi_glu<2>(acc, 3 + i, gp_hi, gp_lo, xp_hi, xp_lo, agg, false);
        __syncthreads();
    }

    // 3 decision steps
#pragma unroll 1
    for (int s = 0; s < 3; s++) {
        // logits = BN(aB @ at_W[s]); aB = X cols 64..127 (byte offset +128)
        gemm_core<64>(xp_hi + 128, xp_lo + 128, 136, WROW_AT + s * 64, ring_s, acc);
        epi_logits(acc, 11 + s, mp_hi, mp_lo);
        __syncthreads();
        sparsemax_phase(s, rowbase, B, mp_hi, mp_lo, inputs);
        __syncthreads();

        gemm_core<256>(mp_hi, mp_lo, 264, WROW_SH0, ring_s, acc);
        epi_glu<0>(acc, 1, gp_hi, gp_lo, xp_hi, xp_lo, agg, false);
        __syncthreads();
        gemm_core<128>(gp_hi, gp_lo, 136, WROW_SH1, ring_s, acc);
        epi_glu<1>(acc, 2, gp_hi, gp_lo, xp_hi, xp_lo, agg, false);
        __syncthreads();
#pragma unroll 1
        for (int i = 0; i < 2; i++) {
            gemm_core<128>(xp_hi, xp_lo, 136, WROW_DEP + ((s + 1) * 2 + i) * 128, ring_s, acc);
            epi_glu<2>(acc, 3 + (s + 1) * 2 + i, gp_hi, gp_lo, xp_hi, xp_lo, agg, i == 1);
            __syncthreads();
        }
    }

    // out = agg @ Wout (64x64), SIMT
    {
        const int c = t & 63;
        const int rg = t >> 6;               // 0..3, 16 rows each
        float acco[16];
#pragma unroll
        for (int rr = 0; rr < 16; rr++) acco[rr] = 0.f;
#pragma unroll 1
        for (int k = 0; k < 64; k++) {
            float wv = Wout[k * 64 + c];
#pragma unroll
            for (int rr = 0; rr < 16; rr++)
                acco[rr] = fmaf(agg[(rg * 16 + rr) * 64 + k], wv, acco[rr]);
        }
#pragma unroll
        for (int rr = 0; rr < 16; rr++) {
            long long gr = rowbase + rg * 16 + rr;
            if (gr < B) out[gr * 64 + c] = acco[rr];
        }
    }
}

extern "C" void kernel_launch(void* const* d_in, const int* in_sizes, int n_in,
                              void* d_out, int out_size)
{
    const float* inputs = (const float*)d_in[0];
    prep_kernel<<<64, 256>>>(
        (const float*)d_in[5], (const float*)d_in[6],   // sh_W0, sh_W1
        (const float*)d_in[11], (const float*)d_in[16], // dep_W, at_W
        (const float*)d_in[1], (const float*)d_in[2], (const float*)d_in[3], (const float*)d_in[4],
        (const float*)d_in[7], (const float*)d_in[8], (const float*)d_in[9], (const float*)d_in[10],
        (const float*)d_in[12], (const float*)d_in[13], (const float*)d_in[14], (const float*)d_in[15],
        (const float*)d_in[17], (const float*)d_in[18], (const float*)d_in[19], (const float*)d_in[20]);

    int B = in_sizes[0] / 256;
    int grid = (B + TB - 1) / TB;
    cudaFuncSetAttribute(tabnet_mma, cudaFuncAttributeMaxDynamicSharedMemorySize, SMEM_TOTAL);
    tabnet_mma<<<grid, NTH, SMEM_TOTAL>>>(inputs, (const float*)d_in[21],
                                          (float*)d_out, B);
}

// round 10
// speedup vs baseline: 2.0715x; 1.0691x over previous
#include <cuda_runtime.h>
#include <cuda_bf16.h>

// TabNet encoder on tensor cores: bf16 hi/lo split mma.sync (3-term compensated).
// CTA = 64 rows, 512 threads (16 warps, 4/SMSP). Warp owns paired n-cols
// (8w, 8w+128) so GLU is lane-local and one ldmatrix.trans fetches both.
// Weights pre-split to bf16 planes, BN pre-folded (prep kernel).
// B=131072, D=256, UN=128, ND=NA=64, NSTEPS=3.

#define TB 64
#define NTH 512
#define CK 32
#define W_ROWS 1600
#define BMAX 131072

#define WROW_SH0 0
#define WROW_SH1 256
#define WROW_DEP 384
#define WROW_AT  1408

__device__ __nv_bfloat16 g_whi[W_ROWS * 256];
__device__ __nv_bfloat16 g_wlo[W_ROWS * 256];
__device__ float2 g_fold[14 * 256];
__device__ float g_prior[(size_t)BMAX * 256];

// smem layout (bytes)
#define OFF_MPH 0          // 64 x 264 bf16
#define OFF_MPL 33792
#define OFF_GPH 67584      // 64 x 136 bf16
#define OFF_GPL 84992
#define OFF_XPH 102400
#define OFF_XPL 119808
#define OFF_AGG 137216     // 64 x 64 f32
#define OFF_RING 153600    // 2 bufs x 2 planes x 32x264 bf16
#define SMEM_TOTAL 221184

__device__ __forceinline__ float sig_(float x) {
    return __fdividef(1.0f, 1.0f + __expf(-x));
}
__device__ __forceinline__ unsigned sptr(const void* p) {
    return (unsigned)__cvta_generic_to_shared(p);
}
__device__ __forceinline__ void cpa16(unsigned s, const void* g) {
    asm volatile("cp.async.cg.shared.global [%0], [%1], 16;" :: "r"(s), "l"(g));
}
__device__ __forceinline__ void cpa_commit() {
    asm volatile("cp.async.commit_group;" ::: "memory");
}
__device__ __forceinline__ void cpa_wait1() {
    asm volatile("cp.async.wait_group 1;" ::: "memory");
}
__device__ __forceinline__ void ldm4(unsigned a, unsigned& r0, unsigned& r1,
                                     unsigned& r2, unsigned& r3) {
    asm volatile("ldmatrix.sync.aligned.m8n8.x4.shared.b16 {%0,%1,%2,%3},[%4];"
                 : "=r"(r0), "=r"(r1), "=r"(r2), "=r"(r3) : "r"(a));
}
__device__ __forceinline__ void ldm4t(unsigned a, unsigned& r0, unsigned& r1,
                                      unsigned& r2, unsigned& r3) {
    asm volatile("ldmatrix.sync.aligned.m8n8.x4.trans.shared.b16 {%0,%1,%2,%3},[%4];"
                 : "=r"(r0), "=r"(r1), "=r"(r2), "=r"(r3) : "r"(a));
}
__device__ __forceinline__ void mma_bf16(float* d, const unsigned* a, const unsigned* b) {
    asm volatile("mma.sync.aligned.m16n8k16.row.col.f32.bf16.bf16.f32 "
                 "{%0,%1,%2,%3},{%4,%5,%6,%7},{%8,%9},{%0,%1,%2,%3};"
                 : "+f"(d[0]), "+f"(d[1]), "+f"(d[2]), "+f"(d[3])
                 : "r"(a[0]), "r"(a[1]), "r"(a[2]), "r"(a[3]), "r"(b[0]), "r"(b[1]));
}
__device__ __forceinline__ void sts32(unsigned a, unsigned v) {
    asm volatile("st.shared.b32 [%0],%1;" :: "r"(a), "r"(v));
}
__device__ __forceinline__ unsigned lds32(unsigned a) {
    unsigned v; asm volatile("ld.shared.b32 %0,[%1];" : "=r"(v) : "r"(a)); return v;
}
__device__ __forceinline__ void sts16(unsigned a, unsigned short v) {
    asm volatile("st.shared.u16 [%0],%1;" :: "r"(a), "h"(v));
}
__device__ __forceinline__ unsigned short lds16(unsigned a) {
    unsigned short v; asm volatile("ld.shared.u16 %0,[%1];" : "=h"(v) : "r"(a)); return v;
}
__device__ __forceinline__ float bfu(unsigned short u) {
    return __bfloat162float(__ushort_as_bfloat16(u));
}
__device__ __forceinline__ void packsplit(float a, float b, unsigned& hi, unsigned& lo) {
    __nv_bfloat16 ah = __float2bfloat16(a), bh = __float2bfloat16(b);
    float la = a - __bfloat162float(ah), lb = b - __bfloat162float(bh);
    hi = (unsigned)__bfloat16_as_ushort(ah) | ((unsigned)__bfloat16_as_ushort(bh) << 16);
    lo = (unsigned)__bfloat16_as_ushort(__float2bfloat16(la))
       | ((unsigned)__bfloat16_as_ushort(__float2bfloat16(lb)) << 16);
}
__device__ __forceinline__ float2 up_pair(unsigned h, unsigned l) {
    return make_float2(bfu((unsigned short)(h & 0xFFFF)) + bfu((unsigned short)(l & 0xFFFF)),
                       bfu((unsigned short)(h >> 16)) + bfu((unsigned short)(l >> 16)));
}

// ---- prep: split weights to bf16 hi/lo planes; fold BN to (scale,bias) ----
__global__ void prep_kernel(const float* __restrict__ sh_W0, const float* __restrict__ sh_W1,
    const float* __restrict__ dep_W, const float* __restrict__ at_W,
    const float* __restrict__ in_g, const float* __restrict__ in_b,
    const float* __restrict__ in_m, const float* __restrict__ in_v,
    const float* __restrict__ sh_g, const float* __restrict__ sh_b,
    const float* __restrict__ sh_m, const float* __restrict__ sh_v,
    const float* __restrict__ dep_g, const float* __restrict__ dep_b,
    const float* __restrict__ dep_m, const float* __restrict__ dep_v,
    const float* __restrict__ at_g, const float* __restrict__ at_b,
    const float* __restrict__ at_m, const float* __restrict__ at_v)
{
    int tid = blockIdx.x * blockDim.x + threadIdx.x;
    int nthr = gridDim.x * blockDim.x;
    for (int i = tid; i < W_ROWS * 256; i += nthr) {
        int row = i >> 8;
        float w;
        if (row < 256)       w = sh_W0[i];
        else if (row < 384)  w = sh_W1[i - 256 * 256];
        else if (row < 1408) w = dep_W[i - 384 * 256];
        else                 w = at_W[i - 1408 * 256];
        __nv_bfloat16 hi = __float2bfloat16(w);
        g_whi[i] = hi;
        g_wlo[i] = __float2bfloat16(w - __bfloat162float(hi));
    }
    for (int i = tid; i < 14 * 256; i += nthr) {
        int l = i >> 8, c = i & 255;
        float g, b, m, v;
        if (l == 0)       { g = in_g[c]; b = in_b[c]; m = in_m[c]; v = in_v[c]; }
        else if (l <= 2)  { int j = (l - 1) * 256 + c;  g = sh_g[j];  b = sh_b[j];  m = sh_m[j];  v = sh_v[j]; }
        else if (l <= 10) { int j = (l - 3) * 256 + c;  g = dep_g[j]; b = dep_b[j]; m = dep_m[j]; v = dep_v[j]; }
        else              { int j = (l - 11) * 256 + c; g = at_g[j];  b = at_b[j];  m = at_m[j];  v = at_v[j]; }
        float sc = g * rsqrtf(v + 1e-3f);
        g_fold[i] = make_float2(sc, b - m * sc);
    }
}

// ---- GEMM core: A(64xK) @ W(Kx256), bf16 split, ring-buffered ----
__device__ __forceinline__ void load_wchunk(int row0, int buf, unsigned ring_s) {
    int t = threadIdx.x;
#pragma unroll
    for (int q = 0; q < 4; q++) {
        int idx = t + NTH * q;               // 0..2047
        int plane = idx >> 10;
        int rem = idx & 1023;
        int row = rem >> 5, seg = rem & 31;
        const __nv_bfloat16* src = (plane ? g_wlo : g_whi) + (row0 + row) * 256 + seg * 8;
        cpa16(ring_s + buf * 33792 + plane * 16896 + (row * 264 + seg * 8) * 2, src);
    }
}

// warp w owns n-cols (8w, 8w+128); acc[m][0]=col 8w tile, acc[m][1]=col 8w+128 tile.
template<int K>
__device__ __forceinline__ void gemm_core(unsigned a_hi, unsigned a_lo, int strideA,
                                          int wrow0, unsigned ring_s, float (&acc)[4][2][4])
{
    const int lane = threadIdx.x & 31;
    const int w = threadIdx.x >> 5;          // 0..15
    const int l15 = lane & 15;
    const int h8 = (lane >> 4) << 3;
    const int bcol = 8 * w + ((lane >> 4) << 7);   // lanes 0-15: col 8w; 16-31: 8w+128
#pragma unroll
    for (int m = 0; m < 4; m++)
#pragma unroll
        for (int n = 0; n < 2; n++)
#pragma unroll
            for (int e = 0; e < 4; e++) acc[m][n][e] = 0.f;

    constexpr int NCH = K / CK;
    load_wchunk(wrow0, 0, ring_s);
    cpa_commit();

#pragma unroll 1
    for (int c = 0; c < NCH; c++) {
        if (c + 1 < NCH) load_wchunk(wrow0 + (c + 1) * CK, (c + 1) & 1, ring_s);
        cpa_commit();
        cpa_wait1();
        __syncthreads();
        unsigned wbh = ring_s + (c & 1) * 33792;
        unsigned wbl = wbh + 16896;
#pragma unroll
        for (int ks = 0; ks < CK / 16; ks++) {
            int k0 = ks * 16;
            unsigned bh[2][2], bl[2][2];
            unsigned boff = (unsigned)(((k0 + l15) * 264 + bcol) * 2);
            ldm4t(wbh + boff, bh[0][0], bh[0][1], bh[1][0], bh[1][1]);
            ldm4t(wbl + boff, bl[0][0], bl[0][1], bl[1][0], bl[1][1]);
#pragma unroll
            for (int m = 0; m < 4; m++) {
                unsigned aoff = (unsigned)(((m * 16 + l15) * strideA + c * CK + k0 + h8) * 2);
                unsigned ah[4], al[4];
                ldm4(a_hi + aoff, ah[0], ah[1], ah[2], ah[3]);
                ldm4(a_lo + aoff, al[0], al[1], al[2], al[3]);
#pragma unroll
                for (int nt = 0; nt < 2; nt++) {
                    mma_bf16(acc[m][nt], ah, bh[nt]);
                    mma_bf16(acc[m][nt], al, bh[nt]);
                    mma_bf16(acc[m][nt], ah, bl[nt]);
                }
            }
        }
        __syncthreads();
    }
}

// ---- epilogues ----
// MODE 0: GLU1 -> G planes.  MODE 1: X = s*(G + GLU2) -> X planes.
// MODE 2: X = s*(X + GLU) in place (+ optional agg += relu(X[:, :64])).
template<int MODE>
__device__ __forceinline__ void epi_glu(float (&acc)[4][2][4], int layer,
                                        unsigned gp_hi, unsigned gp_lo,
                                        unsigned xp_hi, unsigned xp_lo,
                                        float* agg, bool addagg)
{
    const int lane = threadIdx.x & 31;
    const int w = threadIdx.x >> 5;
    const int tig = lane & 3, gid = lane >> 2;
    const int u0 = 8 * w + 2 * tig;
    float2 fa[2], fb[2];
#pragma unroll
    for (int e = 0; e < 2; e++) {
        fa[e] = g_fold[layer * 256 + u0 + e];
        fb[e] = g_fold[layer * 256 + u0 + 128 + e];
    }
#pragma unroll
    for (int m = 0; m < 4; m++)
#pragma unroll
        for (int hh = 0; hh < 2; hh++) {
            int r = m * 16 + gid + 8 * hh;
            float v[2];
#pragma unroll
            for (int e = 0; e < 2; e++) {
                float ha = fmaf(acc[m][0][hh * 2 + e], fa[e].x, fa[e].y);
                float hb = fmaf(acc[m][1][hh * 2 + e], fb[e].x, fb[e].y);
                v[e] = ha * sig_(hb);
            }
            unsigned dsth = ((MODE == 0) ? gp_hi : xp_hi) + (r * 136 + u0) * 2;
            unsigned dstl = ((MODE == 0) ? gp_lo : xp_lo) + (r * 136 + u0) * 2;
            if (MODE == 1) {
                float2 g = up_pair(lds32(gp_hi + (r * 136 + u0) * 2),
                                   lds32(gp_lo + (r * 136 + u0) * 2));
                v[0] = 0.70710678118654752f * (g.x + v[0]);
                v[1] = 0.70710678118654752f * (g.y + v[1]);
            } else if (MODE == 2) {
                float2 x = up_pair(lds32(dsth), lds32(dstl));
                v[0] = 0.70710678118654752f * (x.x + v[0]);
                v[1] = 0.70710678118654752f * (x.y + v[1]);
                if (addagg && u0 < 64) {
                    agg[r * 64 + u0]     += fmaxf(v[0], 0.f);
                    agg[r * 64 + u0 + 1] += fmaxf(v[1], 0.f);
                }
            }
            unsigned ph, pl;
            packsplit(v[0], v[1], ph, pl);
            sts32(dsth, ph);
            sts32(dstl, pl);
        }
}

// logits: BN'd accumulator -> MP planes (warp covers cols 8w and 8w+128)
__device__ __forceinline__ void epi_logits(float (&acc)[4][2][4], int layer,
                                           unsigned mp_hi, unsigned mp_lo)
{
    const int lane = threadIdx.x & 31;
    const int w = threadIdx.x >> 5;
    const int tig = lane & 3, gid = lane >> 2;
#pragma unroll
    for (int m = 0; m < 4; m++)
#pragma unroll
        for (int nt = 0; nt < 2; nt++) {
            int u0 = 8 * w + 2 * tig + nt * 128;
            float2 f0 = g_fold[layer * 256 + u0];
            float2 f1 = g_fold[layer * 256 + u0 + 1];
#pragma unroll
            for (int hh = 0; hh < 2; hh++) {
                int r = m * 16 + gid + 8 * hh;
                float v0 = fmaf(acc[m][nt][hh * 2 + 0], f0.x, f0.y);
                float v1 = fmaf(acc[m][nt][hh * 2 + 1], f1.x, f1.y);
                unsigned ph, pl;
                packsplit(v0, v1, ph, pl);
                sts32(mp_hi + (r * 264 + u0) * 2, ph);
                sts32(mp_lo + (r * 264 + u0) * 2, pl);
            }
        }
}

// sparsemax: z = prior * logits(MP); Michelot; MP <- mask * feat(inputs)
__device__ __forceinline__ void sparsemax_phase(int step, long long rowbase, int B,
                                                unsigned mp_hi, unsigned mp_lo,
                                                const float* __restrict__ inputs)
{
    const int w = threadIdx.x >> 5;          // 0..15 -> 4 rows each
    const int lane = threadIdx.x & 31;
    float2 fin[8];
#pragma unroll
    for (int i = 0; i < 8; i++) fin[i] = g_fold[lane + 32 * i];

#pragma unroll 1
    for (int rr = 0; rr < 4; rr++) {
        int r = w * 4 + rr;
        long long gr = rowbase + r; if (gr >= B) gr = B - 1;
        float* pp = g_prior + gr * 256;
        const float* xin = inputs + gr * 256;

        float pv[8], z[8];
#pragma unroll
        for (int i = 0; i < 8; i++) {
            int e = lane + 32 * i;
            float lg = bfu(lds16(mp_hi + (r * 264 + e) * 2))
                     + bfu(lds16(mp_lo + (r * 264 + e) * 2));
            pv[i] = (step == 0) ? 1.0f : pp[e];
            z[i] = pv[i] * lg;
        }
        unsigned am = 0xFFu;
        float tau = 0.0f;
        for (int it = 0; it < 64; it++) {
            float s = 0.0f, cnt = 0.0f;
#pragma unroll
            for (int i = 0; i < 8; i++)
                if (am & (1u << i)) { s += z[i]; cnt += 1.0f; }
#pragma unroll
            for (int o = 16; o >= 1; o >>= 1) {
                s   += __shfl_xor_sync(0xffffffffu, s, o);
                cnt += __shfl_xor_sync(0xffffffffu, cnt, o);
            }
            tau = __fdividef(s - 1.0f, cnt);
            unsigned na = 0u;
#pragma unroll
            for (int i = 0; i < 8; i++)
                if (z[i] > tau) na |= (1u << i);
            int changed = (na != am);
            am = na;
            if (!__any_sync(0xffffffffu, changed)) break;
        }
#pragma unroll
        for (int i = 0; i < 8; i++) {
            int e = lane + 32 * i;
            float mv = fmaxf(z[i] - tau, 0.0f);
            float feat = fmaf(fin[i].x, xin[e], fin[i].y);
            float o = mv * feat;
            __nv_bfloat16 oh = __float2bfloat16(o);
            sts16(mp_hi + (r * 264 + e) * 2, __bfloat16_as_ushort(oh));
            sts16(mp_lo + (r * 264 + e) * 2,
                  __bfloat16_as_ushort(__float2bfloat16(o - __bfloat162float(oh))));
            if (step < 2) pp[e] = pv[i] * (1.3f - mv);
        }
    }
}

__global__ void __launch_bounds__(NTH, 1)
tabnet_mma(const float* __restrict__ inputs, const float* __restrict__ Wout,
           float* __restrict__ out, int B)
{
    extern __shared__ char sm[];
    const unsigned mp_hi = sptr(sm + OFF_MPH), mp_lo = sptr(sm + OFF_MPL);
    const unsigned gp_hi = sptr(sm + OFF_GPH), gp_lo = sptr(sm + OFF_GPL);
    const unsigned xp_hi = sptr(sm + OFF_XPH), xp_lo = sptr(sm + OFF_XPL);
    float* agg = reinterpret_cast<float*>(sm + OFF_AGG);
    const unsigned ring_s = sptr(sm + OFF_RING);

    const int t = threadIdx.x;
    const long long rowbase = (long long)blockIdx.x * TB;

    // phase 0: feat = BN(input) -> MP planes; agg = 0
    {
        const float4* in4 = reinterpret_cast<const float4*>(inputs);
#pragma unroll
        for (int i = 0; i < 8; i++) {
            int lin = t + NTH * i;           // float4 index over 64 x 64
            int r = lin >> 6, c4 = lin & 63;
            long long gr = rowbase + r; if (gr >= B) gr = B - 1;
            float4 xv = in4[gr * 64 + c4];
            float2 f0 = g_fold[c4 * 4 + 0], f1 = g_fold[c4 * 4 + 1];
            float2 f2 = g_fold[c4 * 4 + 2], f3 = g_fold[c4 * 4 + 3];
            unsigned h01, l01, h23, l23;
            packsplit(fmaf(f0.x, xv.x, f0.y), fmaf(f1.x, xv.y, f1.y), h01, l01);
            packsplit(fmaf(f2.x, xv.z, f2.y), fmaf(f3.x, xv.w, f3.y), h23, l23);
            unsigned base = (unsigned)((r * 264 + c4 * 4) * 2);
            sts32(mp_hi + base, h01); sts32(mp_hi + base + 4, h23);
            sts32(mp_lo + base, l01); sts32(mp_lo + base + 4, l23);
        }
        float4* a4 = reinterpret_cast<float4*>(agg);
#pragma unroll
        for (int i = 0; i < 2; i++)
            a4[t + NTH * i] = make_float4(0.f, 0.f, 0.f, 0.f);
    }
    __syncthreads();

    float acc[4][2][4];

    // initial shared block + dep block
    gemm_core<256>(mp_hi, mp_lo, 264, WROW_SH0, ring_s, acc);
    epi_glu<0>(acc, 1, gp_hi, gp_lo, xp_hi, xp_lo, agg, false);
    __syncthreads();
    gemm_core<128>(gp_hi, gp_lo, 136, WROW_SH1, ring_s, acc);
    epi_glu<1>(acc, 2, gp_hi, gp_lo, xp_hi, xp_lo, agg, false);
    __syncthreads();
#pragma unroll 1
    for (int i = 0; i < 2; i++) {
        gemm_core<128>(xp_hi, xp_lo, 136, WROW_DEP + i * 128, ring_s, acc);
        epi_glu<2>(acc, 3 + i, gp_hi, gp_lo, xp_hi, xp_lo, agg, false);
        __syncthreads();
    }

    // 3 decision steps
#pragma unroll 1
    for (int s = 0; s < 3; s++) {
        // logits = BN(aB @ at_W[s]); aB = X cols 64..127 (byte offset +128)
        gemm_core<64>(xp_hi + 128, xp_lo + 128, 136, WROW_AT + s * 64, ring_s, acc);
        epi_logits(acc, 11 + s, mp_hi, mp_lo);
        __syncthreads();
        sparsemax_phase(s, rowbase, B, mp_hi, mp_lo, inputs);
        __syncthreads();

        gemm_core<256>(mp_hi, mp_lo, 264, WROW_SH0, ring_s, acc);
        epi_glu<0>(acc, 1, gp_hi, gp_lo, xp_hi, xp_lo, agg, false);
        __syncthreads();
        gemm_core<128>(gp_hi, gp_lo, 136, WROW_SH1, ring_s, acc);
        epi_glu<1>(acc, 2, gp_hi, gp_lo, xp_hi, xp_lo, agg, false);
        __syncthreads();
#pragma unroll 1
        for (int i = 0; i < 2; i++) {
            gemm_core<128>(xp_hi, xp_lo, 136, WROW_DEP + ((s + 1) * 2 + i) * 128, ring_s, acc);
            epi_glu<2>(acc, 3 + (s + 1) * 2 + i, gp_hi, gp_lo, xp_hi, xp_lo, agg, i == 1);
            __syncthreads();
        }
    }

    // out = agg @ Wout (64x64), SIMT
    {
        const int c = t & 63;
        const int rg = t >> 6;               // 0..7, 8 rows each
        float acco[8];
#pragma unroll
        for (int rr = 0; rr < 8; rr++) acco[rr] = 0.f;
#pragma unroll 1
        for (int k = 0; k < 64; k++) {
            float wv = Wout[k * 64 + c];
#pragma unroll
            for (int rr = 0; rr < 8; rr++)
                acco[rr] = fmaf(agg[(rg * 8 + rr) * 64 + k], wv, acco[rr]);
        }
#pragma unroll
        for (int rr = 0; rr < 8; rr++) {
            long long gr = rowbase + rg * 8 + rr;
            if (gr < B) out[gr * 64 + c] = acco[rr];
        }
    }
}

extern "C" void kernel_launch(void* const* d_in, const int* in_sizes, int n_in,
                              void* d_out, int out_size)
{
    const float* inputs = (const float*)d_in[0];
    prep_kernel<<<64, 256>>>(
        (const float*)d_in[5], (const float*)d_in[6],   // sh_W0, sh_W1
        (const float*)d_in[11], (const float*)d_in[16], // dep_W, at_W
        (const float*)d_in[1], (const float*)d_in[2], (const float*)d_in[3], (const float*)d_in[4],
        (const float*)d_in[7], (const float*)d_in[8], (const float*)d_in[9], (const float*)d_in[10],
        (const float*)d_in[12], (const float*)d_in[13], (const float*)d_in[14], (const float*)d_in[15],
        (const float*)d_in[17], (const float*)d_in[18], (const float*)d_in[19], (const float*)d_in[20]);

    int B = in_sizes[0] / 256;
    int grid = (B + TB - 1) / TB;
    cudaFuncSetAttribute(tabnet_mma, cudaFuncAttributeMaxDynamicSharedMemorySize, SMEM_TOTAL);
    tabnet_mma<<<grid, NTH, SMEM_TOTAL>>>(inputs, (const float*)d_in[21],
                                          (float*)d_out, B);
}

// round 11
// speedup vs baseline: 2.1680x; 1.0466x over previous
#include <cuda_runtime.h>
#include <cuda_bf16.h>

// TabNet encoder on tensor cores: bf16 hi/lo split mma.sync (3-term compensated).
// 2 CTAs per SM, each CTA = 32 rows / 256 threads (8 warps), independent barrier
// schedules so one CTA's GEMM overlaps the other's epilogue/sparsemax.
// Weights pre-split to bf16 planes, BN pre-folded (prep kernel).
// B=131072, D=256, UN=128, ND=NA=64, NSTEPS=3.

#define TB 32
#define NTH 256
#define CK 16
#define W_ROWS 1600
#define BMAX 131072

#define WROW_SH0 0
#define WROW_SH1 256
#define WROW_DEP 384
#define WROW_AT  1408

__device__ __nv_bfloat16 g_whi[W_ROWS * 256];
__device__ __nv_bfloat16 g_wlo[W_ROWS * 256];
__device__ float2 g_fold[14 * 256];
__device__ float g_prior[(size_t)BMAX * 256];

// smem layout (bytes), per CTA (110592 total -> 2 CTAs/SM)
#define OFF_MPH 0          // 32 x 264 bf16 = 16896
#define OFF_MPL 16896
#define OFF_GPH 33792      // 32 x 136 bf16 = 8704
#define OFF_GPL 42496
#define OFF_XPH 51200
#define OFF_XPL 59904
#define OFF_AGG 68608      // 32 x 64 f32 = 8192
#define OFF_RING 76800     // 2 bufs x 2 planes x 16x264 bf16 = 33792
#define SMEM_TOTAL 110592

__device__ __forceinline__ float sig_(float x) {
    return __fdividef(1.0f, 1.0f + __expf(-x));
}
__device__ __forceinline__ unsigned sptr(const void* p) {
    return (unsigned)__cvta_generic_to_shared(p);
}
__device__ __forceinline__ void cpa16(unsigned s, const void* g) {
    asm volatile("cp.async.cg.shared.global [%0], [%1], 16;" :: "r"(s), "l"(g));
}
__device__ __forceinline__ void cpa_commit() {
    asm volatile("cp.async.commit_group;" ::: "memory");
}
__device__ __forceinline__ void cpa_wait1() {
    asm volatile("cp.async.wait_group 1;" ::: "memory");
}
__device__ __forceinline__ void ldm4(unsigned a, unsigned& r0, unsigned& r1,
                                     unsigned& r2, unsigned& r3) {
    asm volatile("ldmatrix.sync.aligned.m8n8.x4.shared.b16 {%0,%1,%2,%3},[%4];"
                 : "=r"(r0), "=r"(r1), "=r"(r2), "=r"(r3) : "r"(a));
}
__device__ __forceinline__ void ldm4t(unsigned a, unsigned& r0, unsigned& r1,
                                      unsigned& r2, unsigned& r3) {
    asm volatile("ldmatrix.sync.aligned.m8n8.x4.trans.shared.b16 {%0,%1,%2,%3},[%4];"
                 : "=r"(r0), "=r"(r1), "=r"(r2), "=r"(r3) : "r"(a));
}
__device__ __forceinline__ void mma_bf16(float* d, const unsigned* a, const unsigned* b) {
    asm volatile("mma.sync.aligned.m16n8k16.row.col.f32.bf16.bf16.f32 "
                 "{%0,%1,%2,%3},{%4,%5,%6,%7},{%8,%9},{%0,%1,%2,%3};"
                 : "+f"(d[0]), "+f"(d[1]), "+f"(d[2]), "+f"(d[3])
                 : "r"(a[0]), "r"(a[1]), "r"(a[2]), "r"(a[3]), "r"(b[0]), "r"(b[1]));
}
__device__ __forceinline__ void sts32(unsigned a, unsigned v) {
    asm volatile("st.shared.b32 [%0],%1;" :: "r"(a), "r"(v));
}
__device__ __forceinline__ unsigned lds32(unsigned a) {
    unsigned v; asm volatile("ld.shared.b32 %0,[%1];" : "=r"(v) : "r"(a)); return v;
}
__device__ __forceinline__ void sts16(unsigned a, unsigned short v) {
    asm volatile("st.shared.u16 [%0],%1;" :: "r"(a), "h"(v));
}
__device__ __forceinline__ unsigned short lds16(unsigned a) {
    unsigned short v; asm volatile("ld.shared.u16 %0,[%1];" : "=h"(v) : "r"(a)); return v;
}
__device__ __forceinline__ float bfu(unsigned short u) {
    return __bfloat162float(__ushort_as_bfloat16(u));
}
__device__ __forceinline__ void packsplit(float a, float b, unsigned& hi, unsigned& lo) {
    __nv_bfloat16 ah = __float2bfloat16(a), bh = __float2bfloat16(b);
    float la = a - __bfloat162float(ah), lb = b - __bfloat162float(bh);
    hi = (unsigned)__bfloat16_as_ushort(ah) | ((unsigned)__bfloat16_as_ushort(bh) << 16);
    lo = (unsigned)__bfloat16_as_ushort(__float2bfloat16(la))
       | ((unsigned)__bfloat16_as_ushort(__float2bfloat16(lb)) << 16);
}
__device__ __forceinline__ float2 up_pair(unsigned h, unsigned l) {
    return make_float2(bfu((unsigned short)(h & 0xFFFF)) + bfu((unsigned short)(l & 0xFFFF)),
                       bfu((unsigned short)(h >> 16)) + bfu((unsigned short)(l >> 16)));
}

// ---- prep: split weights to bf16 hi/lo planes; fold BN to (scale,bias) ----
__global__ void prep_kernel(const float* __restrict__ sh_W0, const float* __restrict__ sh_W1,
    const float* __restrict__ dep_W, const float* __restrict__ at_W,
    const float* __restrict__ in_g, const float* __restrict__ in_b,
    const float* __restrict__ in_m, const float* __restrict__ in_v,
    const float* __restrict__ sh_g, const float* __restrict__ sh_b,
    const float* __restrict__ sh_m, const float* __restrict__ sh_v,
    const float* __restrict__ dep_g, const float* __restrict__ dep_b,
    const float* __restrict__ dep_m, const float* __restrict__ dep_v,
    const float* __restrict__ at_g, const float* __restrict__ at_b,
    const float* __restrict__ at_m, const float* __restrict__ at_v)
{
    int tid = blockIdx.x * blockDim.x + threadIdx.x;
    int nthr = gridDim.x * blockDim.x;
    for (int i = tid; i < W_ROWS * 256; i += nthr) {
        int row = i >> 8;
        float w;
        if (row < 256)       w = sh_W0[i];
        else if (row < 384)  w = sh_W1[i - 256 * 256];
        else if (row < 1408) w = dep_W[i - 384 * 256];
        else                 w = at_W[i - 1408 * 256];
        __nv_bfloat16 hi = __float2bfloat16(w);
        g_whi[i] = hi;
        g_wlo[i] = __float2bfloat16(w - __bfloat162float(hi));
    }
    for (int i = tid; i < 14 * 256; i += nthr) {
        int l = i >> 8, c = i & 255;
        float g, b, m, v;
        if (l == 0)       { g = in_g[c]; b = in_b[c]; m = in_m[c]; v = in_v[c]; }
        else if (l <= 2)  { int j = (l - 1) * 256 + c;  g = sh_g[j];  b = sh_b[j];  m = sh_m[j];  v = sh_v[j]; }
        else if (l <= 10) { int j = (l - 3) * 256 + c;  g = dep_g[j]; b = dep_b[j]; m = dep_m[j]; v = dep_v[j]; }
        else              { int j = (l - 11) * 256 + c; g = at_g[j];  b = at_b[j];  m = at_m[j];  v = at_v[j]; }
        float sc = g * rsqrtf(v + 1e-3f);
        g_fold[i] = make_float2(sc, b - m * sc);
    }
}

// ---- GEMM core: A(32xK) @ W(Kx256), bf16 split, 16-k double-buffered ring ----
__device__ __forceinline__ void load_wchunk(int row0, int buf, unsigned ring_s) {
    int t = threadIdx.x;
#pragma unroll
    for (int q = 0; q < 4; q++) {
        int idx = t + NTH * q;               // 0..1023 x 16B
        int plane = idx >> 9;
        int rem = idx & 511;
        int row = rem >> 5, seg = rem & 31;
        const __nv_bfloat16* src = (plane ? g_wlo : g_whi) + (row0 + row) * 256 + seg * 8;
        cpa16(ring_s + buf * 16896 + plane * 8448 + (row * 264 + seg * 8) * 2, src);
    }
}

// 8 warps: warp w owns n-cols {16w..16w+15} and {16w+128..16w+143}.
// acc[m][nt]: m=2 (row tiles of 16), nt: 0,1 -> cols 16w+8nt; 2,3 -> +128.
template<int K>
__device__ __forceinline__ void gemm_core(unsigned a_hi, unsigned a_lo, int strideA,
                                          int wrow0, unsigned ring_s, float (&acc)[2][4][4])
{
    const int lane = threadIdx.x & 31;
    const int w = threadIdx.x >> 5;          // 0..7
    const int l15 = lane & 15;
    const int h8 = (lane >> 4) << 3;
#pragma unroll
    for (int m = 0; m < 2; m++)
#pragma unroll
        for (int n = 0; n < 4; n++)
#pragma unroll
            for (int e = 0; e < 4; e++) acc[m][n][e] = 0.f;

    constexpr int NCH = K / CK;
    load_wchunk(wrow0, 0, ring_s);
    cpa_commit();

#pragma unroll 1
    for (int c = 0; c < NCH; c++) {
        if (c + 1 < NCH) load_wchunk(wrow0 + (c + 1) * CK, (c + 1) & 1, ring_s);
        cpa_commit();
        cpa_wait1();
        __syncthreads();
        unsigned wbh = ring_s + (c & 1) * 16896;
        unsigned wbl = wbh + 8448;

        unsigned bh[4][2], bl[4][2];
        unsigned boff = (unsigned)((l15 * 264 + 16 * w + h8) * 2);
        ldm4t(wbh + boff, bh[0][0], bh[0][1], bh[1][0], bh[1][1]);
        ldm4t(wbh + boff + 256, bh[2][0], bh[2][1], bh[3][0], bh[3][1]);
        ldm4t(wbl + boff, bl[0][0], bl[0][1], bl[1][0], bl[1][1]);
        ldm4t(wbl + boff + 256, bl[2][0], bl[2][1], bl[3][0], bl[3][1]);
#pragma unroll
        for (int m = 0; m < 2; m++) {
            unsigned aoff = (unsigned)(((m * 16 + l15) * strideA + c * CK + h8) * 2);
            unsigned ah[4], al[4];
            ldm4(a_hi + aoff, ah[0], ah[1], ah[2], ah[3]);
            ldm4(a_lo + aoff, al[0], al[1], al[2], al[3]);
#pragma unroll
            for (int nt = 0; nt < 4; nt++) {
                mma_bf16(acc[m][nt], ah, bh[nt]);
                mma_bf16(acc[m][nt], al, bh[nt]);
                mma_bf16(acc[m][nt], ah, bl[nt]);
            }
        }
        __syncthreads();
    }
}

// ---- epilogues ----
// MODE 0: GLU1 -> G planes.  MODE 1: X = s*(G + GLU2) -> X planes.
// MODE 2: X = s*(X + GLU) in place (+ optional agg += relu(X[:, :64])).
template<int MODE>
__device__ __forceinline__ void epi_glu(float (&acc)[2][4][4], int layer,
                                        unsigned gp_hi, unsigned gp_lo,
                                        unsigned xp_hi, unsigned xp_lo,
                                        float* agg, bool addagg)
{
    const int lane = threadIdx.x & 31;
    const int w = threadIdx.x >> 5;
    const int tig = lane & 3, gid = lane >> 2;
    float2 fa[2][2], fb[2][2];
#pragma unroll
    for (int j = 0; j < 2; j++)
#pragma unroll
        for (int e = 0; e < 2; e++) {
            int cc = 16 * w + 8 * j + 2 * tig + e;
            fa[j][e] = g_fold[layer * 256 + cc];
            fb[j][e] = g_fold[layer * 256 + cc + 128];
        }
#pragma unroll
    for (int m = 0; m < 2; m++)
#pragma unroll
        for (int j = 0; j < 2; j++)
#pragma unroll
            for (int hh = 0; hh < 2; hh++) {
                int r = m * 16 + gid + 8 * hh;
                int u0 = 16 * w + 8 * j + 2 * tig;
                float v[2];
#pragma unroll
                for (int e = 0; e < 2; e++) {
                    float ha = fmaf(acc[m][j][hh * 2 + e], fa[j][e].x, fa[j][e].y);
                    float hb = fmaf(acc[m][j + 2][hh * 2 + e], fb[j][e].x, fb[j][e].y);
                    v[e] = ha * sig_(hb);
                }
                unsigned dsth = ((MODE == 0) ? gp_hi : xp_hi) + (r * 136 + u0) * 2;
                unsigned dstl = ((MODE == 0) ? gp_lo : xp_lo) + (r * 136 + u0) * 2;
                if (MODE == 1) {
                    float2 g = up_pair(lds32(gp_hi + (r * 136 + u0) * 2),
                                       lds32(gp_lo + (r * 136 + u0) * 2));
                    v[0] = 0.70710678118654752f * (g.x + v[0]);
                    v[1] = 0.70710678118654752f * (g.y + v[1]);
                } else if (MODE == 2) {
                    float2 x = up_pair(lds32(dsth), lds32(dstl));
                    v[0] = 0.70710678118654752f * (x.x + v[0]);
                    v[1] = 0.70710678118654752f * (x.y + v[1]);
                    if (addagg && u0 < 64) {
                        agg[r * 64 + u0]     += fmaxf(v[0], 0.f);
                        agg[r * 64 + u0 + 1] += fmaxf(v[1], 0.f);
                    }
                }
                unsigned ph, pl;
                packsplit(v[0], v[1], ph, pl);
                sts32(dsth, ph);
                sts32(dstl, pl);
            }
}

// logits: BN'd accumulator -> MP planes (all 256 cols, stride 264)
__device__ __forceinline__ void epi_logits(float (&acc)[2][4][4], int layer,
                                           unsigned mp_hi, unsigned mp_lo)
{
    const int lane = threadIdx.x & 31;
    const int w = threadIdx.x >> 5;
    const int tig = lane & 3, gid = lane >> 2;
#pragma unroll
    for (int m = 0; m < 2; m++)
#pragma unroll
        for (int nt = 0; nt < 4; nt++) {
            int cn = (nt < 2) ? (16 * w + 8 * nt) : (128 + 16 * w + 8 * (nt - 2));
            int u0 = cn + 2 * tig;
            float2 f0 = g_fold[layer * 256 + u0];
            float2 f1 = g_fold[layer * 256 + u0 + 1];
#pragma unroll
            for (int hh = 0; hh < 2; hh++) {
                int r = m * 16 + gid + 8 * hh;
                float v0 = fmaf(acc[m][nt][hh * 2 + 0], f0.x, f0.y);
                float v1 = fmaf(acc[m][nt][hh * 2 + 1], f1.x, f1.y);
                unsigned ph, pl;
                packsplit(v0, v1, ph, pl);
                sts32(mp_hi + (r * 264 + u0) * 2, ph);
                sts32(mp_lo + (r * 264 + u0) * 2, pl);
            }
        }
}

// sparsemax: z = prior * logits(MP); Michelot; MP <- mask * feat(inputs)
__device__ __forceinline__ void sparsemax_phase(int step, long long rowbase, int B,
                                                unsigned mp_hi, unsigned mp_lo,
                                                const float* __restrict__ inputs)
{
    const int w = threadIdx.x >> 5;          // 0..7 -> 4 rows each
    const int lane = threadIdx.x & 31;
    float2 fin[8];
#pragma unroll
    for (int i = 0; i < 8; i++) fin[i] = g_fold[lane + 32 * i];

#pragma unroll 1
    for (int rr = 0; rr < 4; rr++) {
        int r = w * 4 + rr;
        long long gr = rowbase + r; if (gr >= B) gr = B - 1;
        float* pp = g_prior + gr * 256;
        const float* xin = inputs + gr * 256;

        float pv[8], z[8];
#pragma unroll
        for (int i = 0; i < 8; i++) {
            int e = lane + 32 * i;
            float lg = bfu(lds16(mp_hi + (r * 264 + e) * 2))
                     + bfu(lds16(mp_lo + (r * 264 + e) * 2));
            pv[i] = (step == 0) ? 1.0f : pp[e];
            z[i] = pv[i] * lg;
        }
        unsigned am = 0xFFu;
        float tau = 0.0f;
        for (int it = 0; it < 64; it++) {
            float s = 0.0f, cnt = 0.0f;
#pragma unroll
            for (int i = 0; i < 8; i++)
                if (am & (1u << i)) { s += z[i]; cnt += 1.0f; }
#pragma unroll
            for (int o = 16; o >= 1; o >>= 1) {
                s   += __shfl_xor_sync(0xffffffffu, s, o);
                cnt += __shfl_xor_sync(0xffffffffu, cnt, o);
            }
            tau = __fdividef(s - 1.0f, cnt);
            unsigned na = 0u;
#pragma unroll
            for (int i = 0; i < 8; i++)
                if (z[i] > tau) na |= (1u << i);
            int changed = (na != am);
            am = na;
            if (!__any_sync(0xffffffffu, changed)) break;
        }
#pragma unroll
        for (int i = 0; i < 8; i++) {
            int e = lane + 32 * i;
            float mv = fmaxf(z[i] - tau, 0.0f);
            float feat = fmaf(fin[i].x, xin[e], fin[i].y);
            float o = mv * feat;
            __nv_bfloat16 oh = __float2bfloat16(o);
            sts16(mp_hi + (r * 264 + e) * 2, __bfloat16_as_ushort(oh));
            sts16(mp_lo + (r * 264 + e) * 2,
                  __bfloat16_as_ushort(__float2bfloat16(o - __bfloat162float(oh))));
            if (step < 2) pp[e] = pv[i] * (1.3f - mv);
        }
    }
}

__global__ void __launch_bounds__(NTH, 2)
tabnet_mma(const float* __restrict__ inputs, const float* __restrict__ Wout,
           float* __restrict__ out, int B)
{
    extern __shared__ char sm[];
    const unsigned mp_hi = sptr(sm + OFF_MPH), mp_lo = sptr(sm + OFF_MPL);
    const unsigned gp_hi = sptr(sm + OFF_GPH), gp_lo = sptr(sm + OFF_GPL);
    const unsigned xp_hi = sptr(sm + OFF_XPH), xp_lo = sptr(sm + OFF_XPL);
    float* agg = reinterpret_cast<float*>(sm + OFF_AGG);
    const unsigned ring_s = sptr(sm + OFF_RING);

    const int t = threadIdx.x;
    const long long rowbase = (long long)blockIdx.x * TB;

    // phase 0: feat = BN(input) -> MP planes; agg = 0
    {
        const float4* in4 = reinterpret_cast<const float4*>(inputs);
#pragma unroll
        for (int i = 0; i < 8; i++) {
            int lin = t + NTH * i;           // float4 index over 32 x 64
            int r = lin >> 6, c4 = lin & 63;
            long long gr = rowbase + r; if (gr >= B) gr = B - 1;
            float4 xv = in4[gr * 64 + c4];
            float2 f0 = g_fold[c4 * 4 + 0], f1 = g_fold[c4 * 4 + 1];
            float2 f2 = g_fold[c4 * 4 + 2], f3 = g_fold[c4 * 4 + 3];
            unsigned h01, l01, h23, l23;
            packsplit(fmaf(f0.x, xv.x, f0.y), fmaf(f1.x, xv.y, f1.y), h01, l01);
            packsplit(fmaf(f2.x, xv.z, f2.y), fmaf(f3.x, xv.w, f3.y), h23, l23);
            unsigned base = (unsigned)((r * 264 + c4 * 4) * 2);
            sts32(mp_hi + base, h01); sts32(mp_hi + base + 4, h23);
            sts32(mp_lo + base, l01); sts32(mp_lo + base + 4, l23);
        }
        float4* a4 = reinterpret_cast<float4*>(agg);
#pragma unroll
        for (int i = 0; i < 2; i++)
            a4[t + NTH * i] = make_float4(0.f, 0.f, 0.f, 0.f);
    }
    __syncthreads();

    float acc[2][4][4];

    // initial shared block + dep block
    gemm_core<256>(mp_hi, mp_lo, 264, WROW_SH0, ring_s, acc);
    epi_glu<0>(acc, 1, gp_hi, gp_lo, xp_hi, xp_lo, agg, false);
    __syncthreads();
    gemm_core<128>(gp_hi, gp_lo, 136, WROW_SH1, ring_s, acc);
    epi_glu<1>(acc, 2, gp_hi, gp_lo, xp_hi, xp_lo, agg, false);
    __syncthreads();
#pragma unroll 1
    for (int i = 0; i < 2; i++) {
        gemm_core<128>(xp_hi, xp_lo, 136, WROW_DEP + i * 128, ring_s, acc);
        epi_glu<2>(acc, 3 + i, gp_hi, gp_lo, xp_hi, xp_lo, agg, false);
        __syncthreads();
    }

    // 3 decision steps
#pragma unroll 1
    for (int s = 0; s < 3; s++) {
        // logits = BN(aB @ at_W[s]); aB = X cols 64..127 (byte offset +128)
        gemm_core<64>(xp_hi + 128, xp_lo + 128, 136, WROW_AT + s * 64, ring_s, acc);
        epi_logits(acc, 11 + s, mp_hi, mp_lo);
        __syncthreads();
        sparsemax_phase(s, rowbase, B, mp_hi, mp_lo, inputs);
        __syncthreads();

        gemm_core<256>(mp_hi, mp_lo, 264, WROW_SH0, ring_s, acc);
        epi_glu<0>(acc, 1, gp_hi, gp_lo, xp_hi, xp_lo, agg, false);
        __syncthreads();
        gemm_core<128>(gp_hi, gp_lo, 136, WROW_SH1, ring_s, acc);
        epi_glu<1>(acc, 2, gp_hi, gp_lo, xp_hi, xp_lo, agg, false);
        __syncthreads();
#pragma unroll 1
        for (int i = 0; i < 2; i++) {
            gemm_core<128>(xp_hi, xp_lo, 136, WROW_DEP + ((s + 1) * 2 + i) * 128, ring_s, acc);
            epi_glu<2>(acc, 3 + (s + 1) * 2 + i, gp_hi, gp_lo, xp_hi, xp_lo, agg, i == 1);
            __syncthreads();
        }
    }

    // out = agg @ Wout (64x64), SIMT
    {
        const int c = t & 63;
        const int rg = t >> 6;               // 0..3, 8 rows each
        float acco[8];
#pragma unroll
        for (int rr = 0; rr < 8; rr++) acco[rr] = 0.f;
#pragma unroll 1
        for (int k = 0; k < 64; k++) {
            float wv = Wout[k * 64 + c];
#pragma unroll
            for (int rr = 0; rr < 8; rr++)
                acco[rr] = fmaf(agg[(rg * 8 + rr) * 64 + k], wv, acco[rr]);
        }
#pragma unroll
        for (int rr = 0; rr < 8; rr++) {
            long long gr = rowbase + rg * 8 + rr;
            if (gr < B) out[gr * 64 + c] = acco[rr];
        }
    }
}

extern "C" void kernel_launch(void* const* d_in, const int* in_sizes, int n_in,
                              void* d_out, int out_size)
{
    const float* inputs = (const float*)d_in[0];
    prep_kernel<<<64, 256>>>(
        (const float*)d_in[5], (const float*)d_in[6],   // sh_W0, sh_W1
        (const float*)d_in[11], (const float*)d_in[16], // dep_W, at_W
        (const float*)d_in[1], (const float*)d_in[2], (const float*)d_in[3], (const float*)d_in[4],
        (const float*)d_in[7], (const float*)d_in[8], (const float*)d_in[9], (const float*)d_in[10],
        (const float*)d_in[12], (const float*)d_in[13], (const float*)d_in[14], (const float*)d_in[15],
        (const float*)d_in[17], (const float*)d_in[18], (const float*)d_in[19], (const float*)d_in[20]);

    int B = in_sizes[0] / 256;
    int grid = (B + TB - 1) / TB;
    cudaFuncSetAttribute(tabnet_mma, cudaFuncAttributeMaxDynamicSharedMemorySize, SMEM_TOTAL);
    tabnet_mma<<<grid, NTH, SMEM_TOTAL>>>(inputs, (const float*)d_in[21],
                                          (float*)d_out, B);
}